// round 2
// baseline (speedup 1.0000x reference)
#include <cuda_runtime.h>
#include <cstdint>

// Problem constants
#define NN 256
#define CC 64
#define TT 64
#define VV 22

// Scratch for x2 (output of the two einsums): N*C*T*V floats = ~92.3 MB
__device__ float g_x2[(size_t)NN * CC * TT * VV];

// ---------------------------------------------------------------------------
// Kernel 1: fused temporal einsum (nctv,vtq->ncqv) + spatial einsum
// (nctv,tvw->nctw). Block handles one n and G=8 channels.
// smem: xs[G][T][V] (45056 B) + tps[T][T] (16384 B, reused as A_eff[V][V])
// ---------------------------------------------------------------------------
#define G1 8

__global__ __launch_bounds__(256, 2)
void st_gcn_graph_kernel(const float* __restrict__ x,
                         const float* __restrict__ Tp,
                         const float* __restrict__ A,
                         const float* __restrict__ Afix)
{
    extern __shared__ float sm[];
    float* xs  = sm;                    // [G1][TT][VV]
    float* tps = sm + G1 * TT * VV;     // [TT][TT], later aliased as Aeff[VV][VV]

    const int n  = blockIdx.x / (CC / G1);
    const int cg = blockIdx.x % (CC / G1);
    const int c0 = cg * G1;
    const int tid = threadIdx.x;

    // Load x tiles for the 8 channels (contiguous in global).
    const float* xbase = x + ((size_t)n * CC + c0) * TT * VV;
    for (int i = tid; i < G1 * TT * VV; i += 256) xs[i] = xbase[i];
    __syncthreads();

    // -------- Stage 1: x1[g][q][v] = sum_t xs[g][t][v] * Tp[v][t][q] --------
    // Thread mapping: q = tid&63 (64 values), gh = tid>>6 handles g=gh, g=gh+4.
    const int q  = tid & 63;
    const int gh = tid >> 6;

    for (int v = 0; v < VV; v++) {
        // load Tp slice for this v: [T][T]
        const float* tpv = Tp + (size_t)v * TT * TT;
        for (int i = tid; i < TT * TT; i += 256) tps[i] = tpv[i];
        __syncthreads();

        const float* xs0 = xs + (size_t)gh       * TT * VV + v;
        const float* xs1 = xs + (size_t)(gh + 4) * TT * VV + v;
        float a0 = 0.f, a1 = 0.f;
        #pragma unroll 8
        for (int t = 0; t < TT; t++) {
            float w = tps[t * TT + q];   // conflict-free (q consecutive)
            a0 = fmaf(xs0[t * VV], w, a0);  // broadcast load
            a1 = fmaf(xs1[t * VV], w, a1);
        }
        __syncthreads();  // all reads of column v done before in-place write
        xs[((size_t)gh       * TT + q) * VV + v] = a0;
        xs[((size_t)(gh + 4) * TT + q) * VV + v] = a1;
        // next iteration's tps load is ordered by the loop-top __syncthreads
        __syncthreads();
    }

    // -------- Stage 2: x2[g][t][w] = sum_v x1[g][t][v] * (A[t]+Afix)[v][w] --
    float* as = tps;  // reuse as Aeff[VV][VV]
    const int w_ = tid % VV;
    const int g  = tid / VV;   // active for tid < G1*VV = 176

    for (int t = 0; t < TT; t++) {
        __syncthreads();
        const float* At = A + (size_t)t * VV * VV;
        for (int i = tid; i < VV * VV; i += 256) as[i] = At[i] + Afix[i];
        __syncthreads();

        if (tid < G1 * VV) {
            const float* xr = xs + ((size_t)g * TT + t) * VV;
            float acc = 0.f;
            #pragma unroll
            for (int v = 0; v < VV; v++)
                acc = fmaf(xr[v], as[v * VV + w_], acc);
            g_x2[(((size_t)n * CC + c0 + g) * TT + t) * VV + w_] = acc;
        }
    }
}

// ---------------------------------------------------------------------------
// Kernel 2: 3x3 conv (same padding) over (T,V) + bias + residual x.
// Block = (t-chunk of 8 rows, n). 256 threads: thread = (co = tid&63,
// two output t-rows), computes all 22 v.
// smem: weights [ci][9][co] = 36864 floats (147456 B) +
//       x2 tile [64][10][24] = 15360 floats (61440 B)   => 208896 B dynamic.
// ---------------------------------------------------------------------------
#define TCHUNK 8

__global__ __launch_bounds__(256, 1)
void st_gcn_conv_kernel(const float* __restrict__ x,
                        const float* __restrict__ Wc,
                        const float* __restrict__ bc,
                        float* __restrict__ y)
{
    extern __shared__ float sm[];
    float* ws = sm;             // ws[(ci*9 + j)*64 + co]
    float* xt = sm + 64 * 9 * 64;  // xt[ci][r(10)][vp(24)]

    const int n  = blockIdx.y;
    const int t0 = blockIdx.x * TCHUNK;
    const int tid = threadIdx.x;

    // Load + transpose weights: Wc[co][ci][j] -> ws[(ci*9+j)*64 + co]
    for (int i = tid; i < 64 * 64 * 9; i += 256) {
        int co = i / 576;
        int r  = i - co * 576;          // ci*9 + j
        ws[r * 64 + co] = Wc[i];
    }
    // Load padded x2 tile: rows t0-1 .. t0+8, cols padded to 24 (vp = v+1)
    for (int i = tid; i < 64 * 10 * 24; i += 256) {
        int ci = i / 240;
        int rr = i - ci * 240;
        int r  = rr / 24;
        int vp = rr - r * 24;
        int t  = t0 - 1 + r;
        int v  = vp - 1;
        float val = 0.f;
        if ((unsigned)t < TT && (unsigned)v < VV)
            val = g_x2[(((size_t)n * CC + ci) * TT + t) * VV + v];
        xt[i] = val;
    }
    __syncthreads();

    const int co = tid & 63;
    const int tp = tid >> 6;     // 0..3
    const int r0 = tp * 2;       // output rows: t0+r0, t0+r0+1

    float acc0[VV], acc1[VV];
    #pragma unroll
    for (int v = 0; v < VV; v++) { acc0[v] = 0.f; acc1[v] = 0.f; }

    for (int ci = 0; ci < 64; ci++) {
        float w[9];
        #pragma unroll
        for (int j = 0; j < 9; j++)
            w[j] = ws[(ci * 9 + j) * 64 + co];   // conflict-free (co consecutive)

        const float* xb = xt + ci * 240;
        #pragma unroll
        for (int rr = 0; rr < 4; rr++) {
            float xr[24];
            #pragma unroll
            for (int k = 0; k < 24; k++)
                xr[k] = xb[(r0 + rr) * 24 + k];  // warp-broadcast loads

            if (rr < 3) {           // contributes to out row t0+r0 with dt = rr
                const int b = rr * 3;
                #pragma unroll
                for (int v = 0; v < VV; v++) {
                    acc0[v] = fmaf(xr[v],     w[b],     acc0[v]);
                    acc0[v] = fmaf(xr[v + 1], w[b + 1], acc0[v]);
                    acc0[v] = fmaf(xr[v + 2], w[b + 2], acc0[v]);
                }
            }
            if (rr >= 1) {          // contributes to out row t0+r0+1 with dt = rr-1
                const int b = (rr - 1) * 3;
                #pragma unroll
                for (int v = 0; v < VV; v++) {
                    acc1[v] = fmaf(xr[v],     w[b],     acc1[v]);
                    acc1[v] = fmaf(xr[v + 1], w[b + 1], acc1[v]);
                    acc1[v] = fmaf(xr[v + 2], w[b + 2], acc1[v]);
                }
            }
        }
    }

    // Epilogue: bias + residual, store both rows.
    const float bias = bc[co];
    {
        size_t base = (((size_t)n * CC + co) * TT + (t0 + r0)) * VV;
        const float* xres = x + base;
        #pragma unroll
        for (int v = 0; v < VV; v++) y[base + v] = acc0[v] + bias + xres[v];
    }
    {
        size_t base = (((size_t)n * CC + co) * TT + (t0 + r0 + 1)) * VV;
        const float* xres = x + base;
        #pragma unroll
        for (int v = 0; v < VV; v++) y[base + v] = acc1[v] + bias + xres[v];
    }
}

// ---------------------------------------------------------------------------
// Launcher
// ---------------------------------------------------------------------------
extern "C" void kernel_launch(void* const* d_in, const int* in_sizes, int n_in,
                              void* d_out, int out_size)
{
    const float* x    = (const float*)d_in[0];
    const float* Tp   = (const float*)d_in[1];
    const float* A    = (const float*)d_in[2];
    const float* Afix = (const float*)d_in[3];
    const float* Wc   = (const float*)d_in[4];
    const float* bc   = (const float*)d_in[5];
    float* y = (float*)d_out;

    const int smem1 = (G1 * TT * VV + TT * TT) * (int)sizeof(float);       // 61440
    const int smem2 = (64 * 9 * 64 + 64 * 10 * 24) * (int)sizeof(float);   // 208896

    cudaFuncSetAttribute(st_gcn_graph_kernel,
                         cudaFuncAttributeMaxDynamicSharedMemorySize, smem1);
    cudaFuncSetAttribute(st_gcn_conv_kernel,
                         cudaFuncAttributeMaxDynamicSharedMemorySize, smem2);

    st_gcn_graph_kernel<<<NN * (CC / G1), 256, smem1>>>(x, Tp, A, Afix);
    st_gcn_conv_kernel<<<dim3(TT / TCHUNK, NN), 256, smem2>>>(x, Wc, bc, y);
}

// round 3
// speedup vs baseline: 1.5976x; 1.5976x over previous
#include <cuda_runtime.h>
#include <cstdint>

// Problem constants
#define NN 256
#define CC 64
#define TT 64
#define VV 22

// Scratch for x2 (output of the two einsums): N*C*T*V floats = ~92.3 MB
__device__ float g_x2[(size_t)NN * CC * TT * VV];

// ---------------------------------------------------------------------------
// Kernel 1: fused temporal einsum (nctv,vtq->ncqv) + spatial einsum
// (nctv,tvw->nctw). Block handles one n and G=8 channels. (unchanged)
// ---------------------------------------------------------------------------
#define G1 8

__global__ __launch_bounds__(256, 2)
void st_gcn_graph_kernel(const float* __restrict__ x,
                         const float* __restrict__ Tp,
                         const float* __restrict__ A,
                         const float* __restrict__ Afix)
{
    extern __shared__ float sm[];
    float* xs  = sm;                    // [G1][TT][VV]
    float* tps = sm + G1 * TT * VV;     // [TT][TT], later aliased as Aeff[VV][VV]

    const int n  = blockIdx.x / (CC / G1);
    const int cg = blockIdx.x % (CC / G1);
    const int c0 = cg * G1;
    const int tid = threadIdx.x;

    const float* xbase = x + ((size_t)n * CC + c0) * TT * VV;
    for (int i = tid; i < G1 * TT * VV; i += 256) xs[i] = xbase[i];
    __syncthreads();

    // -------- Stage 1: x1[g][q][v] = sum_t xs[g][t][v] * Tp[v][t][q] --------
    const int q  = tid & 63;
    const int gh = tid >> 6;

    for (int v = 0; v < VV; v++) {
        const float* tpv = Tp + (size_t)v * TT * TT;
        for (int i = tid; i < TT * TT; i += 256) tps[i] = tpv[i];
        __syncthreads();

        const float* xs0 = xs + (size_t)gh       * TT * VV + v;
        const float* xs1 = xs + (size_t)(gh + 4) * TT * VV + v;
        float a0 = 0.f, a1 = 0.f;
        #pragma unroll 8
        for (int t = 0; t < TT; t++) {
            float w = tps[t * TT + q];
            a0 = fmaf(xs0[t * VV], w, a0);
            a1 = fmaf(xs1[t * VV], w, a1);
        }
        __syncthreads();
        xs[((size_t)gh       * TT + q) * VV + v] = a0;
        xs[((size_t)(gh + 4) * TT + q) * VV + v] = a1;
        __syncthreads();
    }

    // -------- Stage 2: x2[g][t][w] = sum_v x1[g][t][v] * (A[t]+Afix)[v][w] --
    float* as = tps;
    const int w_ = tid % VV;
    const int g  = tid / VV;

    for (int t = 0; t < TT; t++) {
        __syncthreads();
        const float* At = A + (size_t)t * VV * VV;
        for (int i = tid; i < VV * VV; i += 256) as[i] = At[i] + Afix[i];
        __syncthreads();

        if (tid < G1 * VV) {
            const float* xr = xs + ((size_t)g * TT + t) * VV;
            float acc = 0.f;
            #pragma unroll
            for (int v = 0; v < VV; v++)
                acc = fmaf(xr[v], as[v * VV + w_], acc);
            g_x2[(((size_t)n * CC + c0 + g) * TT + t) * VV + w_] = acc;
        }
    }
}

// ---------------------------------------------------------------------------
// Kernel 2: 3x3 conv via tf32 tensor cores (mma.sync.m16n8k8).
// 9-shift implicit GEMM: y[pix, co] = sum_j Wj[ci,co] * Xj[pix,ci]
// where Xj is the padded x2 tile read at (m + off_j) -- M fully contiguous.
// Block = (n, 8-row t chunk). 256 threads = 8 warps.
// Warp tile: 48 positions (3 x m16) x 32 co (4 x n8). K = 64 ci per shift.
// smem: W [9][16][64][4] tf32 (147456 B) + x2 tile [64][248] (+pad) tf32.
// ---------------------------------------------------------------------------
#define TC 8
#define PW 24
#define MPOS (TC * PW)   // 192
#define PLANE 248        // padded plane stride (floats); (24k+g) banks distinct
#define XOFF 8           // data offset within plane (guards col=-1 reads)

__device__ __forceinline__ void mma_tf32(float* c, const uint32_t* a,
                                         uint32_t b0, uint32_t b1) {
    asm volatile(
        "mma.sync.aligned.m16n8k8.row.col.f32.tf32.tf32.f32 "
        "{%0,%1,%2,%3}, {%4,%5,%6,%7}, {%8,%9}, {%0,%1,%2,%3};"
        : "+f"(c[0]), "+f"(c[1]), "+f"(c[2]), "+f"(c[3])
        : "r"(a[0]), "r"(a[1]), "r"(a[2]), "r"(a[3]), "r"(b0), "r"(b1));
}

__device__ __forceinline__ uint32_t f2tf32(float v) {
    uint32_t r;
    asm("cvt.rna.tf32.f32 %0, %1;" : "=r"(r) : "f"(v));
    return r;
}

#define WS_FLOATS (9 * 16 * 64 * 4)          // 36864
#define XT_FLOATS (64 * PLANE + 32)          // 15904 (tail pad for m+off overread)

__global__ __launch_bounds__(256, 1)
void st_gcn_conv_tc(const float* __restrict__ x,
                    const float* __restrict__ Wc,
                    const float* __restrict__ bc,
                    float* __restrict__ y)
{
    extern __shared__ float sm[];
    uint32_t* ws = (uint32_t*)sm;               // [9][ci/4][co][ci%4]
    uint32_t* xt = (uint32_t*)(sm + WS_FLOATS); // [64][PLANE] tf32 (+8 lead pad)

    const int n   = blockIdx.y;
    const int t0  = blockIdx.x * TC;
    const int tid = threadIdx.x;

    // Weights: Wc[co][ci][dt][dv] -> ws[((j*16 + ci/4)*64 + co)*4 + ci%4], tf32
    for (int i = tid; i < 9 * 64 * 64; i += 256) {
        int co = i / 576;
        int r  = i - co * 576;     // ci*9 + j
        int ci = r / 9;
        int j  = r - ci * 9;
        ws[(((j * 16 + (ci >> 2)) * 64 + co) << 2) + (ci & 3)] = f2tf32(Wc[i]);
    }
    // Zero x2 tile (covers lead/tail pads and gap words 240..247 of each plane)
    for (int i = tid; i < XT_FLOATS / 4; i += 256)
        ((uint4*)xt)[i] = make_uint4(0, 0, 0, 0);
    __syncthreads();
    // Fill interior: rows t0-1..t0+8, cols padded to 24 (vp = v+1), tf32
    for (int i = tid; i < 64 * 10 * PW; i += 256) {
        int ci = i / (10 * PW);
        int rr = i - ci * (10 * PW);
        int r  = rr / PW;
        int vp = rr - r * PW;
        int t  = t0 - 1 + r;
        int v  = vp - 1;
        float val = 0.f;
        if ((unsigned)t < TT && (unsigned)v < VV)
            val = g_x2[(((size_t)n * CC + ci) * TT + t) * VV + v];
        xt[ci * PLANE + XOFF + rr] = f2tf32(val);
    }
    __syncthreads();

    const int warp   = tid >> 5;
    const int lane   = tid & 31;
    const int lg     = lane >> 2;   // group id 0..7
    const int lk     = lane & 3;    // thread in group
    const int warp_m = warp >> 1;   // 0..3 : position tile
    const int co0    = (warp & 1) * 32;
    const int m_base = warp_m * 48;

    float acc[3][4][4];
    #pragma unroll
    for (int mt = 0; mt < 3; mt++)
        #pragma unroll
        for (int nt = 0; nt < 4; nt++)
            #pragma unroll
            for (int r = 0; r < 4; r++) acc[mt][nt][r] = 0.f;

    #pragma unroll 1
    for (int j = 0; j < 9; j++) {
        const int offj = XOFF + (j / 3) * PW + (j % 3) - 1;
        const uint32_t* wj = ws + j * 4096;
        const uint32_t* xbase = xt + offj + m_base + lg;

        #pragma unroll
        for (int kc = 0; kc < 8; kc++) {
            // B fragments: 4 n8 tiles (coalesced, conflict-free LDS)
            uint32_t b0[4], b1[4];
            #pragma unroll
            for (int nt = 0; nt < 4; nt++) {
                int co = co0 + nt * 8 + lg;
                b0[nt] = wj[((kc * 2)     * 64 + co) * 4 + lk];
                b1[nt] = wj[((kc * 2 + 1) * 64 + co) * 4 + lk];
            }
            // A fragments: 3 m16 tiles (conflict-free: banks (24*lk+lg)%32 distinct)
            uint32_t a[3][4];
            const uint32_t* p0 = xbase + (kc * 8 + lk) * PLANE;
            const uint32_t* p1 = p0 + 4 * PLANE;
            #pragma unroll
            for (int mt = 0; mt < 3; mt++) {
                a[mt][0] = p0[mt * 16];
                a[mt][1] = p0[mt * 16 + 8];
                a[mt][2] = p1[mt * 16];
                a[mt][3] = p1[mt * 16 + 8];
            }
            #pragma unroll
            for (int mt = 0; mt < 3; mt++)
                #pragma unroll
                for (int nt = 0; nt < 4; nt++)
                    mma_tf32(acc[mt][nt], a[mt], b0[nt], b1[nt]);
        }
    }

    // Epilogue: bias + residual; drop pad columns (vp==0 || vp==23)
    #pragma unroll
    for (int mt = 0; mt < 3; mt++) {
        #pragma unroll
        for (int half = 0; half < 2; half++) {
            int p  = m_base + mt * 16 + lg + half * 8;
            int tt = t0 + p / PW;
            int vp = p % PW;
            if (vp >= 1 && vp <= VV) {
                int v = vp - 1;
                #pragma unroll
                for (int nt = 0; nt < 4; nt++) {
                    #pragma unroll
                    for (int c2 = 0; c2 < 2; c2++) {
                        int co = co0 + nt * 8 + 2 * lk + c2;
                        size_t idx = (((size_t)n * CC + co) * TT + tt) * VV + v;
                        y[idx] = acc[mt][nt][half * 2 + c2] + bc[co] + x[idx];
                    }
                }
            }
        }
    }
}

// ---------------------------------------------------------------------------
// Launcher
// ---------------------------------------------------------------------------
extern "C" void kernel_launch(void* const* d_in, const int* in_sizes, int n_in,
                              void* d_out, int out_size)
{
    const float* x    = (const float*)d_in[0];
    const float* Tp   = (const float*)d_in[1];
    const float* A    = (const float*)d_in[2];
    const float* Afix = (const float*)d_in[3];
    const float* Wc   = (const float*)d_in[4];
    const float* bc   = (const float*)d_in[5];
    float* y = (float*)d_out;

    const int smem1 = (G1 * TT * VV + TT * TT) * (int)sizeof(float);   // 61440
    const int smem2 = (WS_FLOATS + XT_FLOATS) * (int)sizeof(float);    // 211072

    cudaFuncSetAttribute(st_gcn_graph_kernel,
                         cudaFuncAttributeMaxDynamicSharedMemorySize, smem1);
    cudaFuncSetAttribute(st_gcn_conv_tc,
                         cudaFuncAttributeMaxDynamicSharedMemorySize, smem2);

    st_gcn_graph_kernel<<<NN * (CC / G1), 256, smem1>>>(x, Tp, A, Afix);
    st_gcn_conv_tc<<<dim3(TT / TC, NN), 256, smem2>>>(x, Wc, bc, y);
}

// round 4
// speedup vs baseline: 2.5371x; 1.5880x over previous
#include <cuda_runtime.h>
#include <cstdint>

// Problem constants
#define NN 256
#define CC 64
#define TT 64
#define VV 22

// ---------------------------------------------------------------------------
// Device globals (scratch)
// ---------------------------------------------------------------------------
// x2 in padded tf32 layout: [n][ci][t][24]  (col 0 and 23 are zeros)
__device__ uint32_t g_x2p[(size_t)NN * CC * TT * 24];
// weights, tf32, conv-smem layout: ws[((j*16 + ci/4)*64 + co)*4 + ci%4]
__device__ uint32_t g_ws[9 * 64 * 64];
// Aeff padded tf32: [q][24 (v, rows 22-23 zero)][24 (ww, cols 0 & 23 zero)]
__device__ uint32_t g_aeff[64 * 24 * 24];

__device__ __forceinline__ uint32_t f2tf32(float v) {
    uint32_t r;
    asm("cvt.rna.tf32.f32 %0, %1;" : "=r"(r) : "f"(v));
    return r;
}

__device__ __forceinline__ void mma_tf32(float* c, const uint32_t* a,
                                         uint32_t b0, uint32_t b1) {
    asm volatile(
        "mma.sync.aligned.m16n8k8.row.col.f32.tf32.tf32.f32 "
        "{%0,%1,%2,%3}, {%4,%5,%6,%7}, {%8,%9}, {%0,%1,%2,%3};"
        : "+f"(c[0]), "+f"(c[1]), "+f"(c[2]), "+f"(c[3])
        : "r"(a[0]), "r"(a[1]), "r"(a[2]), "r"(a[3]), "r"(b0), "r"(b1));
}

// ---------------------------------------------------------------------------
// Prep kernels
// ---------------------------------------------------------------------------
__global__ void prep_w_kernel(const float* __restrict__ Wc) {
    int i = blockIdx.x * 256 + threadIdx.x;
    if (i >= 9 * 64 * 64) return;
    int co = i / 576;
    int r  = i - co * 576;        // ci*9 + j
    int ci = r / 9;
    int j  = r - ci * 9;
    g_ws[(((j * 16 + (ci >> 2)) * 64 + co) << 2) + (ci & 3)] = f2tf32(Wc[i]);
}

__global__ void prep_a_kernel(const float* __restrict__ A,
                              const float* __restrict__ Afix) {
    int i = blockIdx.x * 256 + threadIdx.x;
    if (i >= 64 * 24 * 24) return;
    int q  = i / 576;
    int r  = i - q * 576;
    int v  = r / 24;
    int ww = r - v * 24;
    uint32_t out = 0;
    if (v < VV && ww >= 1 && ww <= VV) {
        int w = ww - 1;
        out = f2tf32(A[(size_t)q * VV * VV + v * VV + w] + Afix[v * VV + w]);
    }
    g_aeff[i] = out;
}

// ---------------------------------------------------------------------------
// Kernel 1: both einsums on tensor cores. Block = (n, 32 channels).
// smem: 24 v-planes of [32 rows(c) x stride 68 (t/q)], plane stride 2177,
//       + tpb buffer (Tp slice 64x72, reused as Aeff 4x576).
// Stage 1 (per v): x1[c,q] = sum_t xs[c,t] * Tp[v][t,q]   (in-place per plane)
// Stage 2 (per q): x2[c,ww] = sum_v x1[c,q(v-plane)] * Aeff[q][v,ww] -> g_x2p
// ---------------------------------------------------------------------------
#define PLSTRIDE 2177   // v-plane stride (mod 32 == 1)
#define RWSTRIDE 68     // channel-row stride (mod 32 == 4)
#define TPSTRIDE 72     // Tp row stride (mod 32 == 8)
#define SM1_WORDS (24 * PLSTRIDE + 64 * TPSTRIDE)   // 56856 -> 227424 B

__global__ __launch_bounds__(256, 1)
void st_gcn_graph_tc(const float* __restrict__ x,
                     const float* __restrict__ Tp)
{
    extern __shared__ uint32_t xsm[];
    uint32_t* tpb = xsm + 24 * PLSTRIDE;

    const int n   = blockIdx.y;
    const int c0  = blockIdx.x * 32;
    const int tid = threadIdx.x;
    const int warp = tid >> 5;
    const int lane = tid & 31;
    const int lg   = lane >> 2;
    const int lk   = lane & 3;

    // ---- Phase A: load x (tf32-rounded) into v-planes; zero planes 22,23 ---
    const float* xbase = x + ((size_t)n * CC + c0) * TT * VV;
    for (int i = tid; i < 32 * TT * VV; i += 256) {
        int c = i / (TT * VV);
        int r = i - c * (TT * VV);
        int t = r / VV;
        int v = r - t * VV;
        xsm[v * PLSTRIDE + c * RWSTRIDE + t] = f2tf32(xbase[i]);
    }
    for (int i = tid; i < 2 * PLSTRIDE; i += 256)
        xsm[22 * PLSTRIDE + i] = 0;

    // ---- Stage 1: per-v GEMM [32c x 64q x 64t], warp = (m half, q quarter) -
    {
        const int m0 = (warp & 1) * 16;
        const int n0 = (warp >> 1) * 16;
        for (int v = 0; v < VV; v++) {
            const float* tpv = Tp + (size_t)v * TT * TT;
            for (int i = tid; i < TT * TT; i += 256)
                tpb[(i >> 6) * TPSTRIDE + (i & 63)] = f2tf32(tpv[i]);
            __syncthreads();

            float acc[2][4] = {};
            const uint32_t* ap = xsm + v * PLSTRIDE + (m0 + lg) * RWSTRIDE;
            const uint32_t* bp = tpb + n0 + lg;
            #pragma unroll
            for (int kc = 0; kc < 8; kc++) {
                uint32_t a[4];
                a[0] = ap[kc * 8 + lk];
                a[1] = ap[8 * RWSTRIDE + kc * 8 + lk];
                a[2] = ap[kc * 8 + lk + 4];
                a[3] = ap[8 * RWSTRIDE + kc * 8 + lk + 4];
                uint32_t b00 = bp[(kc * 8 + lk) * TPSTRIDE];
                uint32_t b01 = bp[(kc * 8 + lk + 4) * TPSTRIDE];
                uint32_t b10 = bp[(kc * 8 + lk) * TPSTRIDE + 8];
                uint32_t b11 = bp[(kc * 8 + lk + 4) * TPSTRIDE + 8];
                mma_tf32(acc[0], a, b00, b01);
                mma_tf32(acc[1], a, b10, b11);
            }
            __syncthreads();   // all reads of plane v / tpb done

            uint32_t* wp = xsm + v * PLSTRIDE + (m0 + lg) * RWSTRIDE;
            #pragma unroll
            for (int nt = 0; nt < 2; nt++) {
                int col = n0 + nt * 8 + 2 * lk;
                wp[col]                    = f2tf32(acc[nt][0]);
                wp[col + 1]                = f2tf32(acc[nt][1]);
                wp[8 * RWSTRIDE + col]     = f2tf32(acc[nt][2]);
                wp[8 * RWSTRIDE + col + 1] = f2tf32(acc[nt][3]);
            }
        }
    }
    __syncthreads();

    // ---- Stage 2: per-q GEMM [32c x 24ww x 24v], warp = (q mod 4, m half) --
    {
        const int qq  = warp >> 1;
        const int m0  = (warp & 1) * 16;
        for (int qg = 0; qg < 16; qg++) {
            for (int i = tid; i < 4 * 576; i += 256)
                tpb[i] = g_aeff[qg * 4 * 576 + i];
            __syncthreads();

            const int q = qg * 4 + qq;
            float acc[3][4] = {};
            const uint32_t* ap = xsm + (m0 + lg) * RWSTRIDE + q;
            const uint32_t* bp = tpb + qq * 576 + lg;
            #pragma unroll
            for (int ks = 0; ks < 3; ks++) {
                uint32_t a[4];
                a[0] = ap[(ks * 8 + lk) * PLSTRIDE];
                a[1] = ap[(ks * 8 + lk) * PLSTRIDE + 8 * RWSTRIDE];
                a[2] = ap[(ks * 8 + lk + 4) * PLSTRIDE];
                a[3] = ap[(ks * 8 + lk + 4) * PLSTRIDE + 8 * RWSTRIDE];
                #pragma unroll
                for (int nt = 0; nt < 3; nt++) {
                    uint32_t b0 = bp[(ks * 8 + lk) * 24 + nt * 8];
                    uint32_t b1 = bp[(ks * 8 + lk + 4) * 24 + nt * 8];
                    mma_tf32(acc[nt], a, b0, b1);
                }
            }
            uint32_t* outb = g_x2p + (((size_t)n * CC + c0 + m0 + lg) * TT + q) * 24;
            #pragma unroll
            for (int nt = 0; nt < 3; nt++) {
                int col = nt * 8 + 2 * lk;
                outb[col]             = f2tf32(acc[nt][0]);
                outb[col + 1]         = f2tf32(acc[nt][1]);
                outb[12288 + col]     = f2tf32(acc[nt][2]);   // +8 channels
                outb[12288 + col + 1] = f2tf32(acc[nt][3]);
            }
            __syncthreads();
        }
    }
}

// ---------------------------------------------------------------------------
// Kernel 2: 3x3 conv via tf32 mma (9-shift implicit GEMM) + bias + residual.
// Loads now pure uint4 copies from pre-laid-out g_ws / g_x2p.
// ---------------------------------------------------------------------------
#define TC 8
#define PW 24
#define PLANE 248
#define XOFF 8
#define WS_WORDS (9 * 16 * 64 * 4)          // 36864
#define XT_WORDS (64 * PLANE + 32)          // 15904

__global__ __launch_bounds__(256, 1)
void st_gcn_conv_tc(const float* __restrict__ x,
                    const float* __restrict__ bc,
                    float* __restrict__ y)
{
    extern __shared__ uint32_t sm[];
    uint32_t* ws = sm;               // [9][ci/4][co][ci%4]
    uint32_t* xt = sm + WS_WORDS;    // [64][PLANE]

    const int n   = blockIdx.y;
    const int t0  = blockIdx.x * TC;
    const int tid = threadIdx.x;

    // Weights: straight uint4 copy
    {
        const uint4* src = (const uint4*)g_ws;
        uint4* dst = (uint4*)ws;
        for (int i = tid; i < WS_WORDS / 4; i += 256) dst[i] = src[i];
    }
    // Zero xt
    {
        uint4 z = make_uint4(0, 0, 0, 0);
        uint4* dst = (uint4*)xt;
        for (int i = tid; i < XT_WORDS / 4; i += 256) dst[i] = z;
    }
    __syncthreads();
    // Fill interior rows from g_x2p (tf32 bits, already padded in v)
    {
        const uint4* src = (const uint4*)g_x2p;
        uint4* dst = (uint4*)xt;
        for (int i = tid; i < 64 * 10 * 6; i += 256) {
            int ci  = i / 60;
            int rem = i - ci * 60;
            int r   = rem / 6;
            int u   = rem - r * 6;
            int t   = t0 - 1 + r;
            if ((unsigned)t < TT)
                dst[ci * 62 + 2 + r * 6 + u] =
                    src[(((size_t)n * CC + ci) * TT + t) * 6 + u];
        }
    }
    __syncthreads();

    const int warp   = tid >> 5;
    const int lane   = tid & 31;
    const int lg     = lane >> 2;
    const int lk     = lane & 3;
    const int warp_m = warp >> 1;
    const int co0    = (warp & 1) * 32;
    const int m_base = warp_m * 48;

    float acc[3][4][4];
    #pragma unroll
    for (int mt = 0; mt < 3; mt++)
        #pragma unroll
        for (int nt = 0; nt < 4; nt++)
            #pragma unroll
            for (int r = 0; r < 4; r++) acc[mt][nt][r] = 0.f;

    #pragma unroll 1
    for (int j = 0; j < 9; j++) {
        const int offj = XOFF + (j / 3) * PW + (j % 3) - 1;
        const uint32_t* wj = ws + j * 4096;
        const uint32_t* xbase = xt + offj + m_base + lg;

        #pragma unroll
        for (int kc = 0; kc < 8; kc++) {
            uint32_t b0[4], b1[4];
            #pragma unroll
            for (int nt = 0; nt < 4; nt++) {
                int co = co0 + nt * 8 + lg;
                b0[nt] = wj[((kc * 2)     * 64 + co) * 4 + lk];
                b1[nt] = wj[((kc * 2 + 1) * 64 + co) * 4 + lk];
            }
            uint32_t a[3][4];
            const uint32_t* p0 = xbase + (kc * 8 + lk) * PLANE;
            const uint32_t* p1 = p0 + 4 * PLANE;
            #pragma unroll
            for (int mt = 0; mt < 3; mt++) {
                a[mt][0] = p0[mt * 16];
                a[mt][1] = p0[mt * 16 + 8];
                a[mt][2] = p1[mt * 16];
                a[mt][3] = p1[mt * 16 + 8];
            }
            #pragma unroll
            for (int mt = 0; mt < 3; mt++)
                #pragma unroll
                for (int nt = 0; nt < 4; nt++)
                    mma_tf32(acc[mt][nt], a[mt], b0[nt], b1[nt]);
        }
    }

    // Epilogue: bias + residual; drop pad columns
    #pragma unroll
    for (int mt = 0; mt < 3; mt++) {
        #pragma unroll
        for (int half = 0; half < 2; half++) {
            int p  = m_base + mt * 16 + lg + half * 8;
            int tt = t0 + p / PW;
            int vp = p % PW;
            if (vp >= 1 && vp <= VV) {
                int v = vp - 1;
                #pragma unroll
                for (int nt = 0; nt < 4; nt++) {
                    #pragma unroll
                    for (int c2 = 0; c2 < 2; c2++) {
                        int co = co0 + nt * 8 + 2 * lk + c2;
                        size_t idx = (((size_t)n * CC + co) * TT + tt) * VV + v;
                        y[idx] = acc[mt][nt][half * 2 + c2] + bc[co] + x[idx];
                    }
                }
            }
        }
    }
}

// ---------------------------------------------------------------------------
// Launcher
// ---------------------------------------------------------------------------
extern "C" void kernel_launch(void* const* d_in, const int* in_sizes, int n_in,
                              void* d_out, int out_size)
{
    const float* x    = (const float*)d_in[0];
    const float* Tp   = (const float*)d_in[1];
    const float* A    = (const float*)d_in[2];
    const float* Afix = (const float*)d_in[3];
    const float* Wc   = (const float*)d_in[4];
    const float* bc   = (const float*)d_in[5];
    float* y = (float*)d_out;

    const int smem1 = SM1_WORDS * (int)sizeof(uint32_t);               // 227424
    const int smem2 = (WS_WORDS + XT_WORDS) * (int)sizeof(uint32_t);   // 211072

    cudaFuncSetAttribute(st_gcn_graph_tc,
                         cudaFuncAttributeMaxDynamicSharedMemorySize, smem1);
    cudaFuncSetAttribute(st_gcn_conv_tc,
                         cudaFuncAttributeMaxDynamicSharedMemorySize, smem2);

    prep_w_kernel<<<(9 * 64 * 64 + 255) / 256, 256>>>(Wc);
    prep_a_kernel<<<(64 * 24 * 24 + 255) / 256, 256>>>(A, Afix);
    st_gcn_graph_tc<<<dim3(2, NN), 256, smem1>>>(x, Tp);
    st_gcn_conv_tc<<<dim3(TT / TC, NN), 256, smem2>>>(x, bc, y);
}

// round 5
// speedup vs baseline: 4.1379x; 1.6310x over previous
#include <cuda_runtime.h>
#include <cstdint>

// Problem constants
#define NN 256
#define CC 64
#define TT 64
#define VV 22

// ---------------------------------------------------------------------------
// Device globals (scratch)
// ---------------------------------------------------------------------------
// x2 in padded tf32 layout: [n][ci][t][24]  (col 0 and 23 are zeros)
__device__ uint32_t g_x2p[(size_t)NN * CC * TT * 24];
// conv weights, tf32: ws[((j*16 + ci/4)*64 + co)*4 + ci%4]
__device__ uint32_t g_ws[9 * 64 * 64];
// Aeff padded tf32: [q][24 (v, rows 22-23 zero)][24 (ww, cols 0 & 23 zero)]
__device__ uint32_t g_aeff[64 * 24 * 24];
// Tp transposed tf32: [v][q][t] with row stride 68 (cols 64..67 unused)
__device__ uint32_t g_tpp[22 * 64 * 68];

__device__ __forceinline__ uint32_t f2tf32(float v) {
    uint32_t r;
    asm("cvt.rna.tf32.f32 %0, %1;" : "=r"(r) : "f"(v));
    return r;
}

__device__ __forceinline__ void mma_tf32(float* c, const uint32_t* a,
                                         uint32_t b0, uint32_t b1) {
    asm volatile(
        "mma.sync.aligned.m16n8k8.row.col.f32.tf32.tf32.f32 "
        "{%0,%1,%2,%3}, {%4,%5,%6,%7}, {%8,%9}, {%0,%1,%2,%3};"
        : "+f"(c[0]), "+f"(c[1]), "+f"(c[2]), "+f"(c[3])
        : "r"(a[0]), "r"(a[1]), "r"(a[2]), "r"(a[3]), "r"(b0), "r"(b1));
}

// ---------------------------------------------------------------------------
// Prep kernels
// ---------------------------------------------------------------------------
__global__ void prep_w_kernel(const float* __restrict__ Wc) {
    int i = blockIdx.x * 256 + threadIdx.x;
    if (i >= 9 * 64 * 64) return;
    int co = i / 576;
    int r  = i - co * 576;        // ci*9 + j
    int ci = r / 9;
    int j  = r - ci * 9;
    g_ws[(((j * 16 + (ci >> 2)) * 64 + co) << 2) + (ci & 3)] = f2tf32(Wc[i]);
}

__global__ void prep_a_kernel(const float* __restrict__ A,
                              const float* __restrict__ Afix) {
    int i = blockIdx.x * 256 + threadIdx.x;
    if (i >= 64 * 24 * 24) return;
    int q  = i / 576;
    int r  = i - q * 576;
    int v  = r / 24;
    int ww = r - v * 24;
    uint32_t out = 0;
    if (v < VV && ww >= 1 && ww <= VV) {
        int w = ww - 1;
        out = f2tf32(A[(size_t)q * VV * VV + v * VV + w] + Afix[v * VV + w]);
    }
    g_aeff[i] = out;
}

__global__ void prep_tp_kernel(const float* __restrict__ Tp) {
    int i = blockIdx.x * 256 + threadIdx.x;
    if (i >= 22 * 64 * 64) return;
    int v = i / 4096;
    int r = i - v * 4096;
    int t = r >> 6;
    int q = r & 63;
    g_tpp[v * 4352 + q * 68 + t] = f2tf32(Tp[i]);
}

// ---------------------------------------------------------------------------
// Kernel 1: both einsums on tensor cores. Block = (n, 16 channels).
// smem: 22 v-planes of [16 rows(c) x stride 68], plane stride 1089 (95832 B)
//       -> 2 CTAs/SM. B operands (Tp slices, Aeff) read directly from global.
// Stage 1 (per v): x1[c,q] = sum_t xs[c,t]*Tp[v][t,q]  (in-place per plane)
//   8 warps, warp w owns q columns [8w, 8w+8): one m16n8k8 chain of 8 MMAs.
// Stage 2 (per q): x2[c,ww] = sum_v x1[c,v-plane @ col q]*Aeff[q][v,ww]
//   warp w owns q = 8w..8w+7; K=24 (v rows 22,23 come from zero B rows;
//   A plane index clamped to 0 for k>=22 - multiplied by zero). No syncs.
// ---------------------------------------------------------------------------
#define PL 1089                 // v-plane stride (mod 32 == 1)
#define K1_SMEM (22 * PL * 4)   // 95832 B

__global__ __launch_bounds__(256, 2)
void st_gcn_graph_tc(const float* __restrict__ x)
{
    extern __shared__ uint32_t xsm[];

    const int n    = blockIdx.y;
    const int c0   = blockIdx.x * 16;
    const int tid  = threadIdx.x;
    const int warp = tid >> 5;
    const int lane = tid & 31;
    const int lg   = lane >> 2;   // 0..7
    const int lk   = lane & 3;    // 0..3

    // ---- Load x (tf32) into v-planes: xsm[v*PL + c*68 + t] ----
    const float* xb = x + ((size_t)n * CC + c0) * TT * VV;
    for (int i = tid; i < 16 * TT * VV; i += 256) {
        int c = i / (TT * VV);
        int r = i - c * (TT * VV);
        int t = r / VV;
        int v = r - t * VV;
        xsm[v * PL + c * 68 + t] = f2tf32(xb[i]);
    }
    __syncthreads();

    // ---- Stage 1: per-v GEMM [16c x 64q x 64t]; warp = q-eighth ----
    const int n0 = warp * 8;
    for (int v = 0; v < VV; v++) {
        float acc[4] = {};
        const uint32_t* ap = xsm + v * PL + lg * 68;
        const uint32_t* bp = g_tpp + v * 4352 + (n0 + lg) * 68;
        #pragma unroll
        for (int kc = 0; kc < 8; kc++) {
            uint32_t a[4];
            a[0] = ap[kc * 8 + lk];
            a[1] = ap[8 * 68 + kc * 8 + lk];
            a[2] = ap[kc * 8 + lk + 4];
            a[3] = ap[8 * 68 + kc * 8 + lk + 4];
            uint32_t b0 = bp[kc * 8 + lk];       // 32B/row, fully used
            uint32_t b1 = bp[kc * 8 + lk + 4];
            mma_tf32(acc, a, b0, b1);
        }
        __syncthreads();   // all reads of plane v complete before overwrite
        uint32_t* wp = xsm + v * PL + lg * 68 + n0 + 2 * lk;
        wp[0]          = f2tf32(acc[0]);
        wp[1]          = f2tf32(acc[1]);
        wp[8 * 68]     = f2tf32(acc[2]);
        wp[8 * 68 + 1] = f2tf32(acc[3]);
    }
    __syncthreads();

    // ---- Stage 2: per-q GEMM [16c x 24ww x 24v]; warp owns 8 q's ----
    for (int qi = 0; qi < 8; qi++) {
        const int q = warp * 8 + qi;
        float acc[3][4] = {};
        const uint32_t* bq = g_aeff + q * 576;
        #pragma unroll
        for (int ks = 0; ks < 3; ks++) {
            int k0 = ks * 8 + lk;                 // <= 19, always valid
            int k1 = k0 + 4;                      // up to 23
            int p1 = (k1 < VV) ? k1 : 0;          // clamp: B rows 22,23 are 0
            uint32_t a[4];
            const uint32_t* r0 = xsm + k0 * PL + lg * 68 + q;
            const uint32_t* r1 = xsm + p1 * PL + lg * 68 + q;
            a[0] = r0[0];
            a[1] = r0[8 * 68];
            a[2] = r1[0];
            a[3] = r1[8 * 68];
            #pragma unroll
            for (int nt = 0; nt < 3; nt++) {
                uint32_t b0 = bq[k0 * 24 + nt * 8 + lg];
                uint32_t b1 = bq[k1 * 24 + nt * 8 + lg];
                mma_tf32(acc[nt], a, b0, b1);
            }
        }
        uint32_t* ob = g_x2p + (((size_t)n * CC + c0 + lg) * TT + q) * 24;
        #pragma unroll
        for (int nt = 0; nt < 3; nt++) {
            int col = nt * 8 + 2 * lk;
            ob[col]                     = f2tf32(acc[nt][0]);
            ob[col + 1]                 = f2tf32(acc[nt][1]);
            ob[8 * TT * 24 + col]       = f2tf32(acc[nt][2]);   // +8 channels
            ob[8 * TT * 24 + col + 1]   = f2tf32(acc[nt][3]);
        }
    }
}

// ---------------------------------------------------------------------------
// Kernel 2: 3x3 conv via tf32 mma (9-shift implicit GEMM) + bias + residual.
// Weights staged in 3 j-groups (49 KB) -> smem 112.8 KB -> 2 CTAs/SM.
// ---------------------------------------------------------------------------
#define TC 8
#define PW 24
#define PLANE 248
#define XOFF 8
#define WSG_WORDS (3 * 16 * 64 * 4)         // 12288 (one j-group)
#define XT_WORDS (64 * PLANE + 32)          // 15904
#define K2_SMEM ((WSG_WORDS + XT_WORDS) * 4) // 112768 B

__global__ __launch_bounds__(256, 2)
void st_gcn_conv_tc(const float* __restrict__ x,
                    const float* __restrict__ bc,
                    float* __restrict__ y)
{
    extern __shared__ uint32_t sm[];
    uint32_t* ws = sm;               // [3][ci/4][co][ci%4]  (current j-group)
    uint32_t* xt = sm + WSG_WORDS;   // [64][PLANE]

    const int n   = blockIdx.y;
    const int t0  = blockIdx.x * TC;
    const int tid = threadIdx.x;

    // Zero xt
    {
        uint4 z = make_uint4(0, 0, 0, 0);
        uint4* dst = (uint4*)xt;
        for (int i = tid; i < XT_WORDS / 4; i += 256) dst[i] = z;
    }
    __syncthreads();
    // Fill interior rows from g_x2p (tf32 bits, already padded in v)
    {
        const uint4* src = (const uint4*)g_x2p;
        uint4* dst = (uint4*)xt;
        for (int i = tid; i < 64 * 10 * 6; i += 256) {
            int ci  = i / 60;
            int rem = i - ci * 60;
            int r   = rem / 6;
            int u   = rem - r * 6;
            int t   = t0 - 1 + r;
            if ((unsigned)t < TT)
                dst[ci * 62 + 2 + r * 6 + u] =
                    src[(((size_t)n * CC + ci) * TT + t) * 6 + u];
        }
    }

    const int warp   = tid >> 5;
    const int lane   = tid & 31;
    const int lg     = lane >> 2;
    const int lk     = lane & 3;
    const int warp_m = warp >> 1;
    const int co0    = (warp & 1) * 32;
    const int m_base = warp_m * 48;

    float acc[3][4][4];
    #pragma unroll
    for (int mt = 0; mt < 3; mt++)
        #pragma unroll
        for (int nt = 0; nt < 4; nt++)
            #pragma unroll
            for (int r = 0; r < 4; r++) acc[mt][nt][r] = 0.f;

    #pragma unroll 1
    for (int jg = 0; jg < 3; jg++) {
        __syncthreads();   // xt ready (jg=0) / previous group's compute done
        {
            const uint4* src = (const uint4*)(g_ws + jg * WSG_WORDS);
            uint4* dst = (uint4*)ws;
            for (int i = tid; i < WSG_WORDS / 4; i += 256) dst[i] = src[i];
        }
        __syncthreads();

        #pragma unroll
        for (int jj = 0; jj < 3; jj++) {
            const int j = jg * 3 + jj;
            const int offj = XOFF + (j / 3) * PW + (j % 3) - 1;
            const uint32_t* wj = ws + jj * 4096;
            const uint32_t* xbase = xt + offj + m_base + lg;

            #pragma unroll
            for (int kc = 0; kc < 8; kc++) {
                uint32_t b0[4], b1[4];
                #pragma unroll
                for (int nt = 0; nt < 4; nt++) {
                    int co = co0 + nt * 8 + lg;
                    b0[nt] = wj[((kc * 2)     * 64 + co) * 4 + lk];
                    b1[nt] = wj[((kc * 2 + 1) * 64 + co) * 4 + lk];
                }
                uint32_t a[3][4];
                const uint32_t* p0 = xbase + (kc * 8 + lk) * PLANE;
                const uint32_t* p1 = p0 + 4 * PLANE;
                #pragma unroll
                for (int mt = 0; mt < 3; mt++) {
                    a[mt][0] = p0[mt * 16];
                    a[mt][1] = p0[mt * 16 + 8];
                    a[mt][2] = p1[mt * 16];
                    a[mt][3] = p1[mt * 16 + 8];
                }
                #pragma unroll
                for (int mt = 0; mt < 3; mt++)
                    #pragma unroll
                    for (int nt = 0; nt < 4; nt++)
                        mma_tf32(acc[mt][nt], a[mt], b0[nt], b1[nt]);
            }
        }
    }

    // Epilogue: bias + residual; drop pad columns
    #pragma unroll
    for (int mt = 0; mt < 3; mt++) {
        #pragma unroll
        for (int half = 0; half < 2; half++) {
            int p  = m_base + mt * 16 + lg + half * 8;
            int tt = t0 + p / PW;
            int vp = p % PW;
            if (vp >= 1 && vp <= VV) {
                int v = vp - 1;
                #pragma unroll
                for (int nt = 0; nt < 4; nt++) {
                    #pragma unroll
                    for (int c2 = 0; c2 < 2; c2++) {
                        int co = co0 + nt * 8 + 2 * lk + c2;
                        size_t idx = (((size_t)n * CC + co) * TT + tt) * VV + v;
                        y[idx] = acc[mt][nt][half * 2 + c2] + bc[co] + x[idx];
                    }
                }
            }
        }
    }
}

// ---------------------------------------------------------------------------
// Launcher
// ---------------------------------------------------------------------------
extern "C" void kernel_launch(void* const* d_in, const int* in_sizes, int n_in,
                              void* d_out, int out_size)
{
    const float* x    = (const float*)d_in[0];
    const float* Tp   = (const float*)d_in[1];
    const float* A    = (const float*)d_in[2];
    const float* Afix = (const float*)d_in[3];
    const float* Wc   = (const float*)d_in[4];
    const float* bc   = (const float*)d_in[5];
    float* y = (float*)d_out;

    cudaFuncSetAttribute(st_gcn_graph_tc,
                         cudaFuncAttributeMaxDynamicSharedMemorySize, K1_SMEM);
    cudaFuncSetAttribute(st_gcn_conv_tc,
                         cudaFuncAttributeMaxDynamicSharedMemorySize, K2_SMEM);

    prep_w_kernel<<<(9 * 64 * 64 + 255) / 256, 256>>>(Wc);
    prep_a_kernel<<<(64 * 24 * 24 + 255) / 256, 256>>>(A, Afix);
    prep_tp_kernel<<<(22 * 64 * 64 + 255) / 256, 256>>>(Tp);
    st_gcn_graph_tc<<<dim3(4, NN), 256, K1_SMEM>>>(x);
    st_gcn_conv_tc<<<dim3(TT / TC, NN), 256, K2_SMEM>>>(x, bc, y);
}

// round 6
// speedup vs baseline: 6.4882x; 1.5680x over previous
#include <cuda_runtime.h>
#include <cuda_fp16.h>
#include <cstdint>

// Problem constants
#define NN 256
#define CC 64
#define TT 64
#define VV 22

// ---------------------------------------------------------------------------
// Device globals (scratch), all fp16x2-packed (uint32_t words)
// ---------------------------------------------------------------------------
// x2 padded: [n][t][w24(24)][cw(32)] where cw = ci-pair (ci 2cw, 2cw+1)
__device__ uint32_t g_x2ph[(size_t)NN * TT * 24 * 32];
// conv weights: word ((j*4+kc)*8+p)*72 + co = (W[co][ci0][j], W[co][ci0+1][j]),
// ci0 = kc*16 + 2p.  co padded 64->72 for bank-free smem reads.
__device__ uint32_t g_wsh[9 * 4 * 8 * 72];
// Tp pairs along t: word ((v*4+kc)*8+p)*64 + q = (Tp[v][t0][q], Tp[v][t0+1][q])
__device__ uint32_t g_tph[22 * 4 * 8 * 64];
// Aeff^T pairs along v: word ((q*2+kc)*8+p)*24 + w24
//   = (Aeff[v0][w], Aeff[v0+1][w]), v0 = kc*16+2p, w = w24-1 (0 at pads)
__device__ uint32_t g_aeffTh[64 * 2 * 8 * 24 + 64];   // +64 pad (OOB-safe reads)

__device__ __forceinline__ void mma_fp16(float* c, const uint32_t* a,
                                         uint32_t b0, uint32_t b1) {
    asm volatile(
        "mma.sync.aligned.m16n8k16.row.col.f32.f16.f16.f32 "
        "{%0,%1,%2,%3}, {%4,%5,%6,%7}, {%8,%9}, {%0,%1,%2,%3};"
        : "+f"(c[0]), "+f"(c[1]), "+f"(c[2]), "+f"(c[3])
        : "r"(a[0]), "r"(a[1]), "r"(a[2]), "r"(a[3]), "r"(b0), "r"(b1));
}

__device__ __forceinline__ uint32_t pack2(float lo, float hi) {
    __half2 h = __floats2half2_rn(lo, hi);
    return *(uint32_t*)&h;
}

// ---------------------------------------------------------------------------
// Prep kernels
// ---------------------------------------------------------------------------
__global__ void prep_wsh(const float* __restrict__ Wc) {
    int i = blockIdx.x * 256 + threadIdx.x;
    if (i >= 9 * 4 * 8 * 64) return;
    int co = i & 63;
    int p  = (i >> 6) & 7;
    int kc = (i >> 9) & 3;
    int j  = i >> 11;
    int ci0 = kc * 16 + 2 * p;
    float w0 = Wc[co * 576 + ci0 * 9 + j];
    float w1 = Wc[co * 576 + (ci0 + 1) * 9 + j];
    g_wsh[((j * 4 + kc) * 8 + p) * 72 + co] = pack2(w0, w1);
}

__global__ void prep_tph(const float* __restrict__ Tp) {
    int i = blockIdx.x * 256 + threadIdx.x;
    if (i >= 22 * 4 * 8 * 64) return;
    int q  = i & 63;
    int p  = (i >> 6) & 7;
    int kc = (i >> 9) & 3;
    int v  = i >> 11;
    int t0 = kc * 16 + 2 * p;
    float f0 = Tp[v * 4096 + t0 * 64 + q];
    float f1 = Tp[v * 4096 + (t0 + 1) * 64 + q];
    g_tph[i] = pack2(f0, f1);
}

__global__ void prep_aeffTh(const float* __restrict__ A,
                            const float* __restrict__ Afix) {
    int i = blockIdx.x * 256 + threadIdx.x;
    if (i >= 64 * 2 * 8 * 24) return;
    int w24 = i % 24;
    int r   = i / 24;
    int p   = r & 7;
    int kc  = (r >> 3) & 1;
    int q   = r >> 4;
    int v0  = kc * 16 + 2 * p;
    float f0 = 0.f, f1 = 0.f;
    if (w24 >= 1 && w24 <= VV) {
        int w = w24 - 1;
        if (v0 < VV)     f0 = A[q * 484 + v0 * 22 + w] + Afix[v0 * 22 + w];
        if (v0 + 1 < VV) f1 = A[q * 484 + (v0 + 1) * 22 + w] + Afix[(v0 + 1) * 22 + w];
    }
    g_aeffTh[i] = pack2(f0, f1);
}

// ---------------------------------------------------------------------------
// Kernel 1: both einsums, fp16 m16n8k16. Block = (n, 16 channels), 256 thr.
// smem: pin [v=22][c=16][36 words] (t-pairs, stride 36 => banks 4lg+lk) +
//       xout [q=64][196 words] (c*12 + vpair; q-pad 4) = 100864 B, 2 CTA/SM.
// Stage 1: warp owns v (w, w+8, w+16): GEMM [16c x 64q x 64t], no syncs.
// Stage 2: warp owns 8 q: C[w24, c] = Aeff^T[w24,v] * x1[v,c], K=32 (zeros pad),
//          output written as fp16x2 ci-pairs directly into g_x2ph.
// ---------------------------------------------------------------------------
#define PIN_WORDS (22 * 16 * 36)    // 12672
#define XO_QS 196
#define XO_WORDS (64 * XO_QS)       // 12544
#define K1_SMEM ((PIN_WORDS + XO_WORDS) * 4)   // 100864

__global__ __launch_bounds__(256, 2)
void st_gcn_graph_fp16(const float* __restrict__ x)
{
    extern __shared__ uint32_t sm1[];
    uint32_t* pin  = sm1;              // x as fp16 pairs along t
    uint32_t* xout = sm1 + PIN_WORDS;  // x1 as fp16 pairs along v

    const int n    = blockIdx.y;
    const int cb   = blockIdx.x;
    const int c0   = cb * 16;
    const int tid  = threadIdx.x;
    const int warp = tid >> 5;
    const int lane = tid & 31;
    const int lg   = lane >> 2;
    const int lk   = lane & 3;

    // zero xout (covers v=22..23 pairs + pad words)
    for (int i = tid; i < XO_WORDS; i += 256) xout[i] = 0;

    // load x -> pin: word (v*16+c)*36 + tp = (x[c][2tp][v], x[c][2tp+1][v])
    const float* xb = x + ((size_t)n * CC + c0) * TT * VV;
    for (int i = tid; i < 16 * 32 * 22; i += 256) {
        int v  = i % 22;
        int r  = i / 22;
        int tp = r & 31;
        int c  = r >> 5;
        float f0 = xb[(c * 64 + 2 * tp) * 22 + v];
        float f1 = xb[(c * 64 + 2 * tp + 1) * 22 + v];
        pin[(v * 16 + c) * 36 + tp] = pack2(f0, f1);
    }
    __syncthreads();

    // ---- Stage 1 ----
    for (int vi = 0; vi < 3; vi++) {
        int v = warp + vi * 8;
        if (v >= VV) break;
        float acc[8][4] = {};
        const uint32_t* pv = pin + v * 16 * 36;
        const uint32_t* bg = g_tph + v * 4 * 8 * 64;
        #pragma unroll
        for (int kc = 0; kc < 4; kc++) {
            uint32_t a[4];
            a[0] = pv[lg * 36 + kc * 8 + lk];
            a[1] = pv[(lg + 8) * 36 + kc * 8 + lk];
            a[2] = pv[lg * 36 + kc * 8 + lk + 4];
            a[3] = pv[(lg + 8) * 36 + kc * 8 + lk + 4];
            const uint32_t* bk = bg + kc * 8 * 64;
            #pragma unroll
            for (int nt = 0; nt < 8; nt++) {
                uint32_t b0 = bk[lk * 64 + nt * 8 + lg];
                uint32_t b1 = bk[(lk + 4) * 64 + nt * 8 + lg];
                mma_fp16(acc[nt], a, b0, b1);
            }
        }
        // transpose-store: x1 value (c,q) -> xout[q][c*12 + v/2] half (v&1)
        __half* hx = (__half*)xout;
        const int vp = v >> 1, vh = v & 1;
        #pragma unroll
        for (int nt = 0; nt < 8; nt++) {
            int q0 = nt * 8 + 2 * lk;
            hx[(q0 * XO_QS + lg * 12 + vp) * 2 + vh]             = __float2half_rn(acc[nt][0]);
            hx[((q0 + 1) * XO_QS + lg * 12 + vp) * 2 + vh]       = __float2half_rn(acc[nt][1]);
            hx[(q0 * XO_QS + (lg + 8) * 12 + vp) * 2 + vh]       = __float2half_rn(acc[nt][2]);
            hx[((q0 + 1) * XO_QS + (lg + 8) * 12 + vp) * 2 + vh] = __float2half_rn(acc[nt][3]);
        }
    }
    __syncthreads();

    // ---- Stage 2 ----
    for (int qi = 0; qi < 8; qi++) {
        const int q = warp * 8 + qi;
        float acc[2][2][4] = {};
        const uint32_t* xq = xout + q * XO_QS;
        const uint32_t* ag = g_aeffTh + q * 2 * 8 * 24;
        #pragma unroll
        for (int kc = 0; kc < 2; kc++) {
            uint32_t a[2][4];
            #pragma unroll
            for (int mt = 0; mt < 2; mt++) {
                a[mt][0] = ag[(kc * 8 + lk) * 24 + mt * 16 + lg];
                a[mt][1] = ag[(kc * 8 + lk) * 24 + mt * 16 + lg + 8];
                a[mt][2] = ag[(kc * 8 + lk + 4) * 24 + mt * 16 + lg];
                a[mt][3] = ag[(kc * 8 + lk + 4) * 24 + mt * 16 + lg + 8];
            }
            uint32_t b0[2], b1[2];
            #pragma unroll
            for (int nt = 0; nt < 2; nt++) {
                b0[nt] = xq[(nt * 8 + lg) * 12 + kc * 8 + lk];
                b1[nt] = xq[(nt * 8 + lg) * 12 + kc * 8 + lk + 4];
            }
            #pragma unroll
            for (int mt = 0; mt < 2; mt++)
                #pragma unroll
                for (int nt = 0; nt < 2; nt++)
                    mma_fp16(acc[mt][nt], a[mt], b0[nt], b1[nt]);
        }
        // store: C[w24][c pair] -> g_x2ph[n][q][w24][cw]
        size_t base = (((size_t)n * TT + q) * 24) * 32 + cb * 8;
        #pragma unroll
        for (int mt = 0; mt < 2; mt++) {
            #pragma unroll
            for (int nt = 0; nt < 2; nt++) {
                int w24a = mt * 16 + lg;
                g_x2ph[base + (size_t)w24a * 32 + nt * 4 + lk] =
                    pack2(acc[mt][nt][0], acc[mt][nt][1]);
                if (mt == 0)
                    g_x2ph[base + (size_t)(w24a + 8) * 32 + nt * 4 + lk] =
                        pack2(acc[mt][nt][2], acc[mt][nt][3]);
            }
        }
    }
}

// ---------------------------------------------------------------------------
// Kernel 2: 3x3 conv, fp16 m16n8k16, 9-shift implicit GEMM + bias + residual.
// Block = (n, 8 t-rows), 256 thr. smem: ws jgroup [3][4][8][72] (27648 B) +
// xt [240 rows][36 words] +64 pad (34816 B) = 62464 B -> 2+ CTA/SM.
// ---------------------------------------------------------------------------
#define WSG (3 * 4 * 8 * 72)        // 6912 words per j-group
#define XTW (240 * 36 + 64)         // 8704 words
#define K2_SMEM ((WSG + XTW) * 4)   // 62464 B

__global__ __launch_bounds__(256, 2)
void st_gcn_conv_fp16(const float* __restrict__ x,
                      const float* __restrict__ bc,
                      float* __restrict__ y)
{
    extern __shared__ uint32_t sm2[];
    uint32_t* ws = sm2;           // current weight j-group
    uint32_t* xt = sm2 + WSG;     // [row = t*24+w24][ci-pair], stride 36

    const int n   = blockIdx.y;
    const int t0  = blockIdx.x * 8;
    const int tid = threadIdx.x;

    // fill xt: rows t0-1 .. t0+8 (10 t-rows x 24), pure uint4 copies
    {
        uint4* dst = (uint4*)xt;                 // 9 uint4 per row
        const uint4* src = (const uint4*)g_x2ph; // 8 uint4 per (t,w24) row
        for (int i = tid; i < 240 * 8; i += 256) {
            int p = i >> 3, u = i & 7;
            int t = t0 - 1 + p / 24;
            uint4 val = make_uint4(0, 0, 0, 0);
            if ((unsigned)t < TT) {
                int w24 = p % 24;
                val = src[(((size_t)n * TT + t) * 24 + w24) * 8 + u];
            }
            dst[p * 9 + u] = val;
        }
    }

    const int warp   = tid >> 5;
    const int lane   = tid & 31;
    const int lg     = lane >> 2;
    const int lk     = lane & 3;
    const int warp_m = warp >> 1;
    const int co0    = (warp & 1) * 32;
    const int m_base = warp_m * 48;

    float acc[3][4][4] = {};

    #pragma unroll 1
    for (int jg = 0; jg < 3; jg++) {
        __syncthreads();   // xt ready (jg=0) / prior group's MMAs done
        {
            const uint4* srcw = (const uint4*)(g_wsh + jg * WSG);
            uint4* dstw = (uint4*)ws;
            for (int i = tid; i < WSG / 4; i += 256) dstw[i] = srcw[i];
        }
        __syncthreads();

        #pragma unroll
        for (int jj = 0; jj < 3; jj++) {
            const int j  = jg * 3 + jj;
            const int jt = j / 3, jv = j % 3;
            // input row for output pos m: m + jt*24 + jv - 1  (halo baked in)
            const int roff = jt * 24 + jv - 1;
            const uint32_t* wj = ws + jj * (4 * 8 * 72);
            const uint32_t* xbase = xt + (m_base + roff + lg) * 36;

            #pragma unroll
            for (int kc = 0; kc < 4; kc++) {
                uint32_t b0[4], b1[4];
                #pragma unroll
                for (int nt = 0; nt < 4; nt++) {
                    b0[nt] = wj[(kc * 8 + lk) * 72 + co0 + nt * 8 + lg];
                    b1[nt] = wj[(kc * 8 + lk + 4) * 72 + co0 + nt * 8 + lg];
                }
                uint32_t a[3][4];
                #pragma unroll
                for (int mt = 0; mt < 3; mt++) {
                    const uint32_t* pa = xbase + mt * 16 * 36 + kc * 8 + lk;
                    a[mt][0] = pa[0];
                    a[mt][1] = pa[8 * 36];
                    a[mt][2] = pa[4];
                    a[mt][3] = pa[8 * 36 + 4];
                }
                #pragma unroll
                for (int mt = 0; mt < 3; mt++)
                    #pragma unroll
                    for (int nt = 0; nt < 4; nt++)
                        mma_fp16(acc[mt][nt], a[mt], b0[nt], b1[nt]);
            }
        }
    }

    // Epilogue: bias + residual; drop pad columns (vp 0 / 23)
    #pragma unroll
    for (int mt = 0; mt < 3; mt++) {
        #pragma unroll
        for (int half = 0; half < 2; half++) {
            int p  = m_base + mt * 16 + lg + half * 8;
            int tt = t0 + p / 24;
            int vp = p % 24;
            if (vp >= 1 && vp <= VV) {
                int v = vp - 1;
                #pragma unroll
                for (int nt = 0; nt < 4; nt++) {
                    #pragma unroll
                    for (int c2 = 0; c2 < 2; c2++) {
                        int co = co0 + nt * 8 + 2 * lk + c2;
                        size_t idx = (((size_t)n * CC + co) * TT + tt) * VV + v;
                        y[idx] = acc[mt][nt][half * 2 + c2] + bc[co] + x[idx];
                    }
                }
            }
        }
    }
}

// ---------------------------------------------------------------------------
// Launcher
// ---------------------------------------------------------------------------
extern "C" void kernel_launch(void* const* d_in, const int* in_sizes, int n_in,
                              void* d_out, int out_size)
{
    const float* x    = (const float*)d_in[0];
    const float* Tp   = (const float*)d_in[1];
    const float* A    = (const float*)d_in[2];
    const float* Afix = (const float*)d_in[3];
    const float* Wc   = (const float*)d_in[4];
    const float* bc   = (const float*)d_in[5];
    float* y = (float*)d_out;

    cudaFuncSetAttribute(st_gcn_graph_fp16,
                         cudaFuncAttributeMaxDynamicSharedMemorySize, K1_SMEM);
    cudaFuncSetAttribute(st_gcn_conv_fp16,
                         cudaFuncAttributeMaxDynamicSharedMemorySize, K2_SMEM);

    prep_wsh<<<(9 * 4 * 8 * 64 + 255) / 256, 256>>>(Wc);
    prep_tph<<<(22 * 4 * 8 * 64 + 255) / 256, 256>>>(Tp);
    prep_aeffTh<<<(64 * 2 * 8 * 24 + 255) / 256, 256>>>(A, Afix);
    st_gcn_graph_fp16<<<dim3(4, NN), 256, K1_SMEM>>>(x);
    st_gcn_conv_fp16<<<dim3(8, NN), 256, K2_SMEM>>>(x, bc, y);
}

// round 7
// speedup vs baseline: 6.6712x; 1.0282x over previous
#include <cuda_runtime.h>
#include <cuda_fp16.h>
#include <cstdint>

// Problem constants
#define NN 256
#define CC 64
#define TT 64
#define VV 22

// ---------------------------------------------------------------------------
// Device globals (scratch), fp16x2-packed words
// ---------------------------------------------------------------------------
// x2 padded: [n][t][w24(24)][cw(32)] where cw = ci-pair
__device__ uint32_t g_x2ph[(size_t)NN * TT * 24 * 32];
// conv weights, co-major rows for ldmatrix: [j][co][pair ci (32) + 4 pad]
__device__ uint32_t g_wshL[9 * 64 * 36];
// stage1 B fragments: [v][kc][lane][16 words]
//   w0-3: b0 nt0-3, w4-7: b0 nt4-7, w8-11: b1 nt0-3, w12-15: b1 nt4-7
__device__ uint32_t g_tphf[22 * 4 * 32 * 16];
// stage2 A fragments: [q][lane][16 words] = [kc][mt][4 regs], OOB regs zeroed
__device__ uint32_t g_a2f[64 * 32 * 16];

__device__ __forceinline__ void mma_fp16(float* c, const uint32_t* a,
                                         uint32_t b0, uint32_t b1) {
    asm volatile(
        "mma.sync.aligned.m16n8k16.row.col.f32.f16.f16.f32 "
        "{%0,%1,%2,%3}, {%4,%5,%6,%7}, {%8,%9}, {%0,%1,%2,%3};"
        : "+f"(c[0]), "+f"(c[1]), "+f"(c[2]), "+f"(c[3])
        : "r"(a[0]), "r"(a[1]), "r"(a[2]), "r"(a[3]), "r"(b0), "r"(b1));
}

__device__ __forceinline__ uint32_t pack2(float lo, float hi) {
    __half2 h = __floats2half2_rn(lo, hi);
    return *(uint32_t*)&h;
}

__device__ __forceinline__ uint32_t smaddr(const void* p) {
    return (uint32_t)__cvta_generic_to_shared(p);
}

__device__ __forceinline__ void ldmx4(uint32_t* r, uint32_t a) {
    asm volatile(
        "ldmatrix.sync.aligned.m8n8.x4.shared.b16 {%0,%1,%2,%3}, [%4];"
        : "=r"(r[0]), "=r"(r[1]), "=r"(r[2]), "=r"(r[3]) : "r"(a));
}

// ---------------------------------------------------------------------------
// Prep kernels
// ---------------------------------------------------------------------------
__global__ void prep_wshL(const float* __restrict__ Wc) {
    int i = blockIdx.x * 256 + threadIdx.x;
    if (i >= 9 * 64 * 32) return;
    int p  = i & 31;
    int co = (i >> 5) & 63;
    int j  = i >> 11;
    float w0 = Wc[co * 576 + (2 * p) * 9 + j];
    float w1 = Wc[co * 576 + (2 * p + 1) * 9 + j];
    g_wshL[j * 2304 + co * 36 + p] = pack2(w0, w1);
}

__global__ void prep_tphf(const float* __restrict__ Tp) {
    int i = blockIdx.x * 256 + threadIdx.x;
    if (i >= 22 * 4 * 32 * 16) return;
    int w    = i & 15;
    int lane = (i >> 4) & 31;
    int kc   = (i >> 9) & 3;
    int v    = i >> 11;
    int lg = lane >> 2, lk = lane & 3;
    int nt   = w & 7;
    int bsel = w >> 3;
    int P  = kc * 8 + lk + bsel * 4;   // t-pair
    int t0 = 2 * P;
    int q  = nt * 8 + lg;
    g_tphf[i] = pack2(Tp[v * 4096 + t0 * 64 + q],
                      Tp[v * 4096 + (t0 + 1) * 64 + q]);
}

__global__ void prep_a2f(const float* __restrict__ A,
                         const float* __restrict__ Afix) {
    int i = blockIdx.x * 256 + threadIdx.x;
    if (i >= 64 * 32 * 16) return;
    int w    = i & 15;
    int lane = (i >> 4) & 31;
    int q    = i >> 9;
    int kc = w >> 3, r = w & 7, mt = r >> 2, ri = r & 3;
    int lg = lane >> 2, lk = lane & 3;
    uint32_t val = 0;
    if (!(mt == 1 && (ri & 1))) {      // rows m>=24 are discarded: keep zero
        int P   = kc * 8 + lk + ((ri >= 2) ? 4 : 0);   // v-pair
        int w24 = mt * 16 + lg + ((ri & 1) ? 8 : 0);
        int v0 = 2 * P, v1 = 2 * P + 1;
        float f0 = 0.f, f1 = 0.f;
        if (w24 >= 1 && w24 <= VV) {
            int ww = w24 - 1;
            if (v0 < VV) f0 = A[q * 484 + v0 * 22 + ww] + Afix[v0 * 22 + ww];
            if (v1 < VV) f1 = A[q * 484 + v1 * 22 + ww] + Afix[v1 * 22 + ww];
        }
        val = pack2(f0, f1);
    }
    g_a2f[i] = val;
}

// ---------------------------------------------------------------------------
// Kernel 1: both einsums, fp16 m16n8k16. Block = (n, 16 channels), 256 thr.
// smem: pin [v=22][c=16][36 words] (t-pairs) + xout [q=64][197 words].
// Stage 1: warp owns v-PAIR (2p, 2p+1): 2 GEMMs [16c x 64q x 64t] in 2 q-passes,
//   results packed (v-even, v-odd) -> xout via 32-bit STS. ldmatrix A loads,
//   fragment-packed global B loads. No syncs inside.
// Stage 2: warp owns 8 q: C[w24, c] = Aeff^T * x1; A frags = 4 LDG.128 from
//   g_a2f; B = conflict-free LDS from xout; output -> g_x2ph as ci-pairs.
// ---------------------------------------------------------------------------
#define PIN_WORDS (22 * 576)        // 12672
#define XO_S 197
#define XO_WORDS (64 * XO_S)        // 12608
#define K1_SMEM ((PIN_WORDS + XO_WORDS) * 4)   // 101120

__global__ __launch_bounds__(256, 2)
void st_gcn_graph_fp16(const float* __restrict__ x)
{
    extern __shared__ uint32_t sm1[];
    uint32_t* pin  = sm1;
    uint32_t* xout = sm1 + PIN_WORDS;

    const int n    = blockIdx.y;
    const int cb   = blockIdx.x;
    const int c0   = cb * 16;
    const int tid  = threadIdx.x;
    const int warp = tid >> 5;
    const int lane = tid & 31;
    const int lg   = lane >> 2;
    const int lk   = lane & 3;

    // zero the 20 xout words per q that are read but never written
    for (int i = tid; i < 64 * 20; i += 256) {
        int q = i / 20, j = i - q * 20;
        int off = (j < 16) ? j * 12 + 11 : 192 + (j - 16);
        xout[q * XO_S + off] = 0;
    }

    // load x -> pin[(v*16+c)*36 + tp] = (x[c][2tp][v], x[c][2tp+1][v])
    const float* xb = x + ((size_t)n * CC + c0) * TT * VV;
    for (int i = tid; i < 16 * 32 * 11; i += 256) {
        int vp2 = i % 11;
        int r   = i / 11;
        int tp  = r & 31;
        int c   = r >> 5;
        float2 a = *((const float2*)(xb + (size_t)(c * 64 + 2 * tp) * 22) + vp2);
        float2 b = *((const float2*)(xb + (size_t)(c * 64 + 2 * tp + 1) * 22) + vp2);
        pin[((2 * vp2) * 16 + c) * 36 + tp]     = pack2(a.x, b.x);
        pin[((2 * vp2 + 1) * 16 + c) * 36 + tp] = pack2(a.y, b.y);
    }
    __syncthreads();

    // ldmatrix lane geometry (A fragments)
    const int arow  = (lane & 7) + ((lane >> 3) & 1) * 8;
    const int kword = (lane >> 4) * 4;
    const uint32_t pinA = smaddr(pin) + (arow * 36 + kword) * 4;

    // ---- Stage 1: v-pair GEMMs ----
    for (int pr = warp; pr < 11; pr += 8) {
        const int v0 = 2 * pr;
        #pragma unroll 1
        for (int pass = 0; pass < 2; pass++) {
            float acc0[4][4] = {}, acc1[4][4] = {};
            #pragma unroll
            for (int kc = 0; kc < 4; kc++) {
                uint32_t a0[4], a1[4];
                ldmx4(a0, pinA + (v0 * 576 + kc * 8) * 4);
                ldmx4(a1, pinA + ((v0 + 1) * 576 + kc * 8) * 4);
                const uint4* f0 = ((const uint4*)g_tphf) + ((v0 * 4 + kc) * 32 + lane) * 4;
                const uint4* f1 = ((const uint4*)g_tphf) + (((v0 + 1) * 4 + kc) * 32 + lane) * 4;
                uint4 B00 = f0[pass], B01 = f0[2 + pass];
                uint4 B10 = f1[pass], B11 = f1[2 + pass];
                const uint32_t* w00 = (const uint32_t*)&B00;
                const uint32_t* w01 = (const uint32_t*)&B01;
                const uint32_t* w10 = (const uint32_t*)&B10;
                const uint32_t* w11 = (const uint32_t*)&B11;
                #pragma unroll
                for (int nt = 0; nt < 4; nt++) {
                    mma_fp16(acc0[nt], a0, w00[nt], w01[nt]);
                    mma_fp16(acc1[nt], a1, w10[nt], w11[nt]);
                }
            }
            #pragma unroll
            for (int nt = 0; nt < 4; nt++) {
                int q0 = (pass * 4 + nt) * 8 + 2 * lk;
                uint32_t* o = xout + q0 * XO_S + lg * 12 + pr;
                o[0]          = pack2(acc0[nt][0], acc1[nt][0]);
                o[XO_S]       = pack2(acc0[nt][1], acc1[nt][1]);
                o[96]         = pack2(acc0[nt][2], acc1[nt][2]);
                o[XO_S + 96]  = pack2(acc0[nt][3], acc1[nt][3]);
            }
        }
    }
    __syncthreads();

    // ---- Stage 2 ----
    #pragma unroll 1
    for (int qi = 0; qi < 8; qi++) {
        const int q = warp * 8 + qi;
        const uint4* af = ((const uint4*)g_a2f) + (q * 32 + lane) * 4;
        uint4 A0 = af[0], A1 = af[1], A2 = af[2], A3 = af[3];
        float acc[2][2][4] = {};
        const uint32_t* xq = xout + q * XO_S;
        #pragma unroll
        for (int kc = 0; kc < 2; kc++) {
            const uint32_t* Am0 = kc ? (const uint32_t*)&A2 : (const uint32_t*)&A0;
            const uint32_t* Am1 = kc ? (const uint32_t*)&A3 : (const uint32_t*)&A1;
            #pragma unroll
            for (int nt = 0; nt < 2; nt++) {
                uint32_t b0 = xq[(nt * 8 + lg) * 12 + kc * 8 + lk];
                uint32_t b1 = xq[(nt * 8 + lg) * 12 + kc * 8 + lk + 4];
                mma_fp16(acc[0][nt], Am0, b0, b1);
                mma_fp16(acc[1][nt], Am1, b0, b1);
            }
        }
        size_t base = (((size_t)n * TT + q) * 24) * 32 + cb * 8;
        #pragma unroll
        for (int mt = 0; mt < 2; mt++) {
            #pragma unroll
            for (int nt = 0; nt < 2; nt++) {
                int w24a = mt * 16 + lg;
                g_x2ph[base + (size_t)w24a * 32 + nt * 4 + lk] =
                    pack2(acc[mt][nt][0], acc[mt][nt][1]);
                if (mt == 0)
                    g_x2ph[base + (size_t)(w24a + 8) * 32 + nt * 4 + lk] =
                        pack2(acc[mt][nt][2], acc[mt][nt][3]);
            }
        }
    }
}

// ---------------------------------------------------------------------------
// Kernel 2: 3x3 conv, fp16 m16n8k16, 9-shift implicit GEMM, ldmatrix operands.
// Block = (n, 8 t-rows), 256 thr. smem: ws j-group [3][64][36] (27648 B) +
// xt [240 rows][36 words] + 64 pad (34816 B) = 62464 B -> 2 CTA/SM.
// ---------------------------------------------------------------------------
#define WSG (3 * 64 * 36)           // 6912 words per j-group
#define XTW (240 * 36 + 64)         // 8704 words
#define K2_SMEM ((WSG + XTW) * 4)   // 62464 B

__global__ __launch_bounds__(256, 2)
void st_gcn_conv_fp16(const float* __restrict__ x,
                      const float* __restrict__ bc,
                      float* __restrict__ y)
{
    extern __shared__ uint32_t sm2[];
    uint32_t* ws = sm2;           // current weight j-group (co-major rows)
    uint32_t* xt = sm2 + WSG;     // [row = t*24+w24][ci-pair], stride 36

    const int n   = blockIdx.y;
    const int t0  = blockIdx.x * 8;
    const int tid = threadIdx.x;

    // fill xt: rows t0-1 .. t0+8 (10 t-rows x 24), pure uint4 copies
    {
        uint4* dst = (uint4*)xt;
        const uint4* src = (const uint4*)g_x2ph;
        for (int i = tid; i < 240 * 8; i += 256) {
            int p = i >> 3, u = i & 7;
            int t = t0 - 1 + p / 24;
            uint4 val = make_uint4(0, 0, 0, 0);
            if ((unsigned)t < TT) {
                int w24 = p % 24;
                val = src[(((size_t)n * TT + t) * 24 + w24) * 8 + u];
            }
            dst[p * 9 + u] = val;
        }
    }

    const int warp   = tid >> 5;
    const int lane   = tid & 31;
    const int lg     = lane >> 2;
    const int lk     = lane & 3;
    const int warp_m = warp >> 1;
    const int co0    = (warp & 1) * 32;
    const int m_base = warp_m * 48;

    // ldmatrix lane geometry
    const int arow  = (lane & 7) + ((lane >> 3) & 1) * 8;
    const int kword = (lane >> 4) * 4;
    const uint32_t xtA = smaddr(xt) + (arow * 36 + kword) * 4;
    const int g     = lane >> 3;
    const int bsel  = g >> 1;                 // nt within pair
    const int bcol  = (g & 1) * 4;
    const uint32_t wsb = smaddr(ws);
    uint32_t bBase[2];
    #pragma unroll
    for (int u = 0; u < 2; u++)
        bBase[u] = wsb + ((co0 + (u * 2 + bsel) * 8 + (lane & 7)) * 36 + bcol) * 4;

    float acc[3][4][4] = {};

    #pragma unroll 1
    for (int jg = 0; jg < 3; jg++) {
        __syncthreads();   // xt ready (jg=0) / prior group's MMAs done
        {
            const uint4* srcw = (const uint4*)(g_wshL + jg * WSG);
            uint4* dstw = (uint4*)ws;
            for (int i = tid; i < WSG / 4; i += 256) dstw[i] = srcw[i];
        }
        __syncthreads();

        #pragma unroll
        for (int jj = 0; jj < 3; jj++) {
            const int j  = jg * 3 + jj;
            const int roff = (j / 3) * 24 + (j % 3) - 1;
            const int mrow0 = m_base + roff;

            #pragma unroll
            for (int kc = 0; kc < 4; kc++) {
                uint32_t a[3][4];
                #pragma unroll
                for (int mt = 0; mt < 3; mt++)
                    ldmx4(a[mt], xtA + ((mrow0 + mt * 16) * 36 + kc * 8) * 4);
                #pragma unroll
                for (int u = 0; u < 2; u++) {
                    uint32_t bb[4];
                    ldmx4(bb, bBase[u] + (jj * 2304 + kc * 8) * 4);
                    #pragma unroll
                    for (int mt = 0; mt < 3; mt++) {
                        mma_fp16(acc[mt][u * 2],     a[mt], bb[0], bb[1]);
                        mma_fp16(acc[mt][u * 2 + 1], a[mt], bb[2], bb[3]);
                    }
                }
            }
        }
    }

    // Epilogue: bias + residual; drop pad columns (vp 0 / 23)
    #pragma unroll
    for (int mt = 0; mt < 3; mt++) {
        #pragma unroll
        for (int half = 0; half < 2; half++) {
            int p  = m_base + mt * 16 + lg + half * 8;
            int tt = t0 + p / 24;
            int vp = p % 24;
            if (vp >= 1 && vp <= VV) {
                int v = vp - 1;
                #pragma unroll
                for (int nt = 0; nt < 4; nt++) {
                    #pragma unroll
                    for (int c2 = 0; c2 < 2; c2++) {
                        int co = co0 + nt * 8 + 2 * lk + c2;
                        size_t idx = (((size_t)n * CC + co) * TT + tt) * VV + v;
                        y[idx] = acc[mt][nt][half * 2 + c2] + bc[co] + x[idx];
                    }
                }
            }
        }
    }
}

// ---------------------------------------------------------------------------
// Launcher
// ---------------------------------------------------------------------------
extern "C" void kernel_launch(void* const* d_in, const int* in_sizes, int n_in,
                              void* d_out, int out_size)
{
    const float* x    = (const float*)d_in[0];
    const float* Tp   = (const float*)d_in[1];
    const float* A    = (const float*)d_in[2];
    const float* Afix = (const float*)d_in[3];
    const float* Wc   = (const float*)d_in[4];
    const float* bc   = (const float*)d_in[5];
    float* y = (float*)d_out;

    cudaFuncSetAttribute(st_gcn_graph_fp16,
                         cudaFuncAttributeMaxDynamicSharedMemorySize, K1_SMEM);
    cudaFuncSetAttribute(st_gcn_conv_fp16,
                         cudaFuncAttributeMaxDynamicSharedMemorySize, K2_SMEM);

    prep_wshL<<<(9 * 64 * 32 + 255) / 256, 256>>>(Wc);
    prep_tphf<<<(22 * 4 * 32 * 16 + 255) / 256, 256>>>(Tp);
    prep_a2f<<<(64 * 32 * 16 + 255) / 256, 256>>>(A, Afix);
    st_gcn_graph_fp16<<<dim3(4, NN), 256, K1_SMEM>>>(x);
    st_gcn_conv_fp16<<<dim3(8, NN), 256, K2_SMEM>>>(x, bc, y);
}

// round 8
// speedup vs baseline: 7.3213x; 1.0974x over previous
#include <cuda_runtime.h>
#include <cuda_fp16.h>
#include <cstdint>

// Problem constants
#define NN 256
#define CC 64
#define TT 64
#define VV 22

// ---------------------------------------------------------------------------
// Device globals (scratch), fp16x2-packed words
// ---------------------------------------------------------------------------
// x2 padded: [n][t][w24(24)][cw(32)] where cw = ci-pair
__device__ uint32_t g_x2ph[(size_t)NN * TT * 24 * 32];
// conv weights, co-major rows for ldmatrix: [j][co][pair ci (32) + 4 pad]
__device__ uint32_t g_wshL[9 * 64 * 36];
// stage1 B fragments: [v][kc][lane][16 words]
__device__ uint32_t g_tphf[22 * 4 * 32 * 16];
// stage2 A fragments: [q][lane][16 words] = [kc][mt][4 regs], OOB regs zeroed
__device__ uint32_t g_a2f[64 * 32 * 16];

__device__ __forceinline__ void mma_fp16(float* c, const uint32_t* a,
                                         uint32_t b0, uint32_t b1) {
    asm volatile(
        "mma.sync.aligned.m16n8k16.row.col.f32.f16.f16.f32 "
        "{%0,%1,%2,%3}, {%4,%5,%6,%7}, {%8,%9}, {%0,%1,%2,%3};"
        : "+f"(c[0]), "+f"(c[1]), "+f"(c[2]), "+f"(c[3])
        : "r"(a[0]), "r"(a[1]), "r"(a[2]), "r"(a[3]), "r"(b0), "r"(b1));
}

__device__ __forceinline__ uint32_t pack2(float lo, float hi) {
    __half2 h = __floats2half2_rn(lo, hi);
    return *(uint32_t*)&h;
}

__device__ __forceinline__ uint32_t smaddr(const void* p) {
    return (uint32_t)__cvta_generic_to_shared(p);
}

__device__ __forceinline__ void ldmx4(uint32_t* r, uint32_t a) {
    asm volatile(
        "ldmatrix.sync.aligned.m8n8.x4.shared.b16 {%0,%1,%2,%3}, [%4];"
        : "=r"(r[0]), "=r"(r[1]), "=r"(r[2]), "=r"(r[3]) : "r"(a));
}

__device__ __forceinline__ void cp16(uint32_t dst, const void* src, int srcsz) {
    asm volatile("cp.async.ca.shared.global [%0], [%1], 16, %2;"
                 :: "r"(dst), "l"(src), "r"(srcsz) : "memory");
}

// ---------------------------------------------------------------------------
// Prep kernels (unchanged)
// ---------------------------------------------------------------------------
__global__ void prep_wshL(const float* __restrict__ Wc) {
    int i = blockIdx.x * 256 + threadIdx.x;
    if (i >= 9 * 64 * 32) return;
    int p  = i & 31;
    int co = (i >> 5) & 63;
    int j  = i >> 11;
    float w0 = Wc[co * 576 + (2 * p) * 9 + j];
    float w1 = Wc[co * 576 + (2 * p + 1) * 9 + j];
    g_wshL[j * 2304 + co * 36 + p] = pack2(w0, w1);
}

__global__ void prep_tphf(const float* __restrict__ Tp) {
    int i = blockIdx.x * 256 + threadIdx.x;
    if (i >= 22 * 4 * 32 * 16) return;
    int w    = i & 15;
    int lane = (i >> 4) & 31;
    int kc   = (i >> 9) & 3;
    int v    = i >> 11;
    int lg = lane >> 2, lk = lane & 3;
    int nt   = w & 7;
    int bsel = w >> 3;
    int P  = kc * 8 + lk + bsel * 4;
    int t0 = 2 * P;
    int q  = nt * 8 + lg;
    g_tphf[i] = pack2(Tp[v * 4096 + t0 * 64 + q],
                      Tp[v * 4096 + (t0 + 1) * 64 + q]);
}

__global__ void prep_a2f(const float* __restrict__ A,
                         const float* __restrict__ Afix) {
    int i = blockIdx.x * 256 + threadIdx.x;
    if (i >= 64 * 32 * 16) return;
    int w    = i & 15;
    int lane = (i >> 4) & 31;
    int q    = i >> 9;
    int kc = w >> 3, r = w & 7, mt = r >> 2, ri = r & 3;
    int lg = lane >> 2, lk = lane & 3;
    uint32_t val = 0;
    if (!(mt == 1 && (ri & 1))) {
        int P   = kc * 8 + lk + ((ri >= 2) ? 4 : 0);
        int w24 = mt * 16 + lg + ((ri & 1) ? 8 : 0);
        int v0 = 2 * P, v1 = 2 * P + 1;
        float f0 = 0.f, f1 = 0.f;
        if (w24 >= 1 && w24 <= VV) {
            int ww = w24 - 1;
            if (v0 < VV) f0 = A[q * 484 + v0 * 22 + ww] + Afix[v0 * 22 + ww];
            if (v1 < VV) f1 = A[q * 484 + v1 * 22 + ww] + Afix[(v1) * 22 + ww];
        }
        val = pack2(f0, f1);
    }
    g_a2f[i] = val;
}

// ---------------------------------------------------------------------------
// Kernel 1: both einsums, fp16 m16n8k16, with ILP improvements.
// ---------------------------------------------------------------------------
#define PIN_WORDS (22 * 576)        // 12672
#define XO_S 197
#define XO_WORDS (64 * XO_S)        // 12608
#define K1_SMEM ((PIN_WORDS + XO_WORDS) * 4)   // 101120

__global__ __launch_bounds__(256, 2)
void st_gcn_graph_fp16(const float* __restrict__ x)
{
    extern __shared__ uint32_t sm1[];
    uint32_t* pin  = sm1;
    uint32_t* xout = sm1 + PIN_WORDS;

    const int n    = blockIdx.y;
    const int cb   = blockIdx.x;
    const int c0   = cb * 16;
    const int tid  = threadIdx.x;
    const int warp = tid >> 5;
    const int lane = tid & 31;
    const int lg   = lane >> 2;
    const int lk   = lane & 3;

    // zero the 20 xout words per q that are read but never written
    for (int i = tid; i < 64 * 20; i += 256) {
        int q = i / 20, j = i - q * 20;
        int off = (j < 16) ? j * 12 + 11 : 192 + (j - 16);
        xout[q * XO_S + off] = 0;
    }

    // load x -> pin[(v*16+c)*36 + tp] = (x[c][2tp][v], x[c][2tp+1][v])
    const float* xb = x + ((size_t)n * CC + c0) * TT * VV;
    for (int i = tid; i < 16 * 32 * 11; i += 256) {
        int vp2 = i % 11;
        int r   = i / 11;
        int tp  = r & 31;
        int c   = r >> 5;
        float2 a = *((const float2*)(xb + (size_t)(c * 64 + 2 * tp) * 22) + vp2);
        float2 b = *((const float2*)(xb + (size_t)(c * 64 + 2 * tp + 1) * 22) + vp2);
        pin[((2 * vp2) * 16 + c) * 36 + tp]     = pack2(a.x, b.x);
        pin[((2 * vp2 + 1) * 16 + c) * 36 + tp] = pack2(a.y, b.y);
    }
    __syncthreads();

    const int arow  = (lane & 7) + ((lane >> 3) & 1) * 8;
    const int kword = (lane >> 4) * 4;
    const uint32_t pinA = smaddr(pin) + (arow * 36 + kword) * 4;

    // ---- Stage 1: v-pair GEMMs, A hoisted, passes unrolled ----
    for (int pr = warp; pr < 11; pr += 8) {
        const int v0 = 2 * pr;
        uint32_t a0[4][4], a1[4][4];
        #pragma unroll
        for (int kc = 0; kc < 4; kc++) {
            ldmx4(a0[kc], pinA + (v0 * 576 + kc * 8) * 4);
            ldmx4(a1[kc], pinA + ((v0 + 1) * 576 + kc * 8) * 4);
        }
        #pragma unroll
        for (int pass = 0; pass < 2; pass++) {
            float acc0[4][4] = {}, acc1[4][4] = {};
            #pragma unroll
            for (int kc = 0; kc < 4; kc++) {
                const uint4* f0 = ((const uint4*)g_tphf) + ((v0 * 4 + kc) * 32 + lane) * 4;
                const uint4* f1 = f0 + 512;
                uint4 B00 = f0[pass], B01 = f0[2 + pass];
                uint4 B10 = f1[pass], B11 = f1[2 + pass];
                const uint32_t* w00 = (const uint32_t*)&B00;
                const uint32_t* w01 = (const uint32_t*)&B01;
                const uint32_t* w10 = (const uint32_t*)&B10;
                const uint32_t* w11 = (const uint32_t*)&B11;
                #pragma unroll
                for (int nt = 0; nt < 4; nt++) {
                    mma_fp16(acc0[nt], a0[kc], w00[nt], w01[nt]);
                    mma_fp16(acc1[nt], a1[kc], w10[nt], w11[nt]);
                }
            }
            #pragma unroll
            for (int nt = 0; nt < 4; nt++) {
                int q0 = (pass * 4 + nt) * 8 + 2 * lk;
                uint32_t* o = xout + q0 * XO_S + lg * 12 + pr;
                o[0]          = pack2(acc0[nt][0], acc1[nt][0]);
                o[XO_S]       = pack2(acc0[nt][1], acc1[nt][1]);
                o[96]         = pack2(acc0[nt][2], acc1[nt][2]);
                o[XO_S + 96]  = pack2(acc0[nt][3], acc1[nt][3]);
            }
        }
    }
    __syncthreads();

    // ---- Stage 2: register-prefetched A fragments, batched B LDS ----
    const uint4* afb = ((const uint4*)g_a2f) + ((warp * 8) * 32 + lane) * 4;
    uint4 A0 = afb[0], A1 = afb[1], A2 = afb[2], A3 = afb[3];
    #pragma unroll 1
    for (int qi = 0; qi < 8; qi++) {
        const int q = warp * 8 + qi;
        uint4 N0, N1, N2, N3;
        if (qi < 7) {
            const uint4* nf = afb + (qi + 1) * 128;
            N0 = nf[0]; N1 = nf[1]; N2 = nf[2]; N3 = nf[3];
        }
        const uint32_t* xq = xout + q * XO_S;
        uint32_t b[2][2][2];
        #pragma unroll
        for (int kc = 0; kc < 2; kc++)
            #pragma unroll
            for (int nt = 0; nt < 2; nt++) {
                b[kc][nt][0] = xq[(nt * 8 + lg) * 12 + kc * 8 + lk];
                b[kc][nt][1] = xq[(nt * 8 + lg) * 12 + kc * 8 + lk + 4];
            }
        float acc[2][2][4] = {};
        #pragma unroll
        for (int kc = 0; kc < 2; kc++) {
            const uint32_t* Am0 = kc ? (const uint32_t*)&A2 : (const uint32_t*)&A0;
            const uint32_t* Am1 = kc ? (const uint32_t*)&A3 : (const uint32_t*)&A1;
            #pragma unroll
            for (int nt = 0; nt < 2; nt++) {
                mma_fp16(acc[0][nt], Am0, b[kc][nt][0], b[kc][nt][1]);
                mma_fp16(acc[1][nt], Am1, b[kc][nt][0], b[kc][nt][1]);
            }
        }
        size_t base = (((size_t)n * TT + q) * 24) * 32 + cb * 8;
        #pragma unroll
        for (int mt = 0; mt < 2; mt++) {
            #pragma unroll
            for (int nt = 0; nt < 2; nt++) {
                int w24a = mt * 16 + lg;
                g_x2ph[base + (size_t)w24a * 32 + nt * 4 + lk] =
                    pack2(acc[mt][nt][0], acc[mt][nt][1]);
                if (mt == 0)
                    g_x2ph[base + (size_t)(w24a + 8) * 32 + nt * 4 + lk] =
                        pack2(acc[mt][nt][2], acc[mt][nt][3]);
            }
        }
        A0 = N0; A1 = N1; A2 = N2; A3 = N3;
    }
}

// ---------------------------------------------------------------------------
// Kernel 2: persistent 3x3 conv, fp16 m16n8k16, weights resident in smem,
// cp.async double-buffered x2 tiles. Grid = 148 CTAs x 512 threads.
// Tile = (n, 16 t-rows): M = 384 positions, N = 64 co, K = 576.
// smem: ws[9][64][36] (82944 B) + 2 x tile buffer (guard36 + 432x36 + guard36).
// ---------------------------------------------------------------------------
#define CTC 16
#define CROWS 432                       // 18 t-rows x 24
#define WS_ALL (9 * 64 * 36)            // 20736 words
#define BUFW (CROWS * 36 + 72)          // 15624 words (guards front+back)
#define K2_SMEM ((WS_ALL + 2 * BUFW) * 4)   // 207936 B
#define NTILES (4 * NN)                 // 1024
#define NSM 148

__global__ __launch_bounds__(512, 1)
void st_gcn_conv_fp16(const float* __restrict__ x,
                      const float* __restrict__ bc,
                      float* __restrict__ y)
{
    extern __shared__ uint32_t sm2[];
    uint32_t* ws = sm2;
    const int tid = threadIdx.x;

    // Load ALL weights once
    {
        const uint4* src = (const uint4*)g_wshL;
        uint4* dst = (uint4*)ws;
        for (int i = tid; i < WS_ALL / 4; i += 512) dst[i] = src[i];
    }

    const int warp   = tid >> 5;
    const int lane   = tid & 31;
    const int lg     = lane >> 2;
    const int lk     = lane & 3;
    const int warp_m = warp >> 1;            // 0..7
    const int co0    = (warp & 1) * 32;
    const int m_base = warp_m * 48;

    const int arow  = (lane & 7) + ((lane >> 3) & 1) * 8;
    const int kword = (lane >> 4) * 4;
    const int g     = lane >> 3;
    const int bsel  = g >> 1;
    const int bcol  = (g & 1) * 4;
    const uint32_t wsb = smaddr(ws);
    uint32_t bBase[2];
    #pragma unroll
    for (int u = 0; u < 2; u++)
        bBase[u] = wsb + ((co0 + (u * 2 + bsel) * 8 + (lane & 7)) * 36 + bcol) * 4;

    const uint32_t smb = smaddr(sm2);

    // tile fill via cp.async (zero-fill for halo t rows)
    auto fill = [&](int b, int tile) {
        const int n  = tile >> 2;
        const int t0 = (tile & 3) * CTC;
        const uint32_t dstb = smb + (WS_ALL + b * BUFW + 36) * 4;
        const uint4* srcn = (const uint4*)g_x2ph + ((size_t)n * TT * 24) * 8;
        for (int i = tid; i < CROWS * 8; i += 512) {
            int r = i >> 3, u = i & 7;
            int tr = r / 24;
            int w24 = r - tr * 24;
            int t = t0 - 1 + tr;
            bool ok = ((unsigned)t < (unsigned)TT);
            const uint4* src = srcn + (((size_t)(ok ? t : 0)) * 24 + w24) * 8 + u;
            cp16(dstb + (r * 36 + u * 4) * 4, src, ok ? 16 : 0);
        }
    };

    int tile = blockIdx.x;
    if (tile < NTILES) fill(0, tile);
    asm volatile("cp.async.commit_group;" ::: "memory");
    __syncthreads();   // weights visible

    int buf = 0;
    for (; tile < NTILES; tile += NSM) {
        int nxt = tile + NSM;
        if (nxt < NTILES) fill(buf ^ 1, nxt);
        asm volatile("cp.async.commit_group;" ::: "memory");
        asm volatile("cp.async.wait_group 1;" ::: "memory");
        __syncthreads();

        const int n  = tile >> 2;
        const int t0 = (tile & 3) * CTC;
        const uint32_t xtA = smb + (WS_ALL + buf * BUFW + 36) * 4
                             + (arow * 36 + kword) * 4;

        float acc[3][4][4] = {};
        #pragma unroll 3
        for (int j = 0; j < 9; j++) {
            const int roff = (j / 3) * 24 + (j % 3) - 1;
            const int mrow0 = m_base + roff;
            #pragma unroll
            for (int kc = 0; kc < 4; kc++) {
                uint32_t a[3][4];
                #pragma unroll
                for (int mt = 0; mt < 3; mt++)
                    ldmx4(a[mt], xtA + ((mrow0 + mt * 16) * 36 + kc * 8) * 4);
                #pragma unroll
                for (int u = 0; u < 2; u++) {
                    uint32_t bb[4];
                    ldmx4(bb, bBase[u] + (j * 2304 + kc * 8) * 4);
                    #pragma unroll
                    for (int mt = 0; mt < 3; mt++) {
                        mma_fp16(acc[mt][u * 2],     a[mt], bb[0], bb[1]);
                        mma_fp16(acc[mt][u * 2 + 1], a[mt], bb[2], bb[3]);
                    }
                }
            }
        }

        // Epilogue: bias + residual; drop pad columns
        #pragma unroll
        for (int mt = 0; mt < 3; mt++) {
            #pragma unroll
            for (int half = 0; half < 2; half++) {
                int p  = m_base + mt * 16 + lg + half * 8;
                int tt = t0 + p / 24;
                int vp = p % 24;
                if (vp >= 1 && vp <= VV) {
                    int v = vp - 1;
                    #pragma unroll
                    for (int nt = 0; nt < 4; nt++) {
                        #pragma unroll
                        for (int c2 = 0; c2 < 2; c2++) {
                            int co = co0 + nt * 8 + 2 * lk + c2;
                            size_t idx = (((size_t)n * CC + co) * TT + tt) * VV + v;
                            y[idx] = acc[mt][nt][half * 2 + c2] + bc[co] + x[idx];
                        }
                    }
                }
            }
        }
        __syncthreads();   // all reads of buf done before it is refilled
        buf ^= 1;
    }
}

// ---------------------------------------------------------------------------
// Launcher
// ---------------------------------------------------------------------------
extern "C" void kernel_launch(void* const* d_in, const int* in_sizes, int n_in,
                              void* d_out, int out_size)
{
    const float* x    = (const float*)d_in[0];
    const float* Tp   = (const float*)d_in[1];
    const float* A    = (const float*)d_in[2];
    const float* Afix = (const float*)d_in[3];
    const float* Wc   = (const float*)d_in[4];
    const float* bc   = (const float*)d_in[5];
    float* y = (float*)d_out;

    cudaFuncSetAttribute(st_gcn_graph_fp16,
                         cudaFuncAttributeMaxDynamicSharedMemorySize, K1_SMEM);
    cudaFuncSetAttribute(st_gcn_conv_fp16,
                         cudaFuncAttributeMaxDynamicSharedMemorySize, K2_SMEM);

    prep_wshL<<<(9 * 64 * 32 + 255) / 256, 256>>>(Wc);
    prep_tphf<<<(22 * 4 * 32 * 16 + 255) / 256, 256>>>(Tp);
    prep_a2f<<<(64 * 32 * 16 + 255) / 256, 256>>>(A, Afix);
    st_gcn_graph_fp16<<<dim3(4, NN), 256, K1_SMEM>>>(x);
    st_gcn_conv_fp16<<<NSM, 512, K2_SMEM>>>(x, bc, y);
}